// round 11
// baseline (speedup 1.0000x reference)
#include <cuda_runtime.h>
#include <math.h>

// ---------------- problem constants ----------------
#define BB   4
#define TT   827
#define CC   256
#define HH   8
#define DHH  32
#define LL   12
#define FF   1024            // 4*C
#define MM   (BB*TT)         // 3308 rows
#define VOC  16384
#define QKVN 768

// ---------------- scratch (device globals; no allocs allowed) ----------------
__device__ float g_x   [MM*CC];
__device__ float g_xn  [MM*CC];
__device__ float g_qkv [MM*QKVN];
__device__ float g_y   [MM*CC];
__device__ float g_ffn [MM*FF];
__device__ float g_h   [(long)BB*TT*TT];   // additive attention bias (even layers)
__device__ float g_z1  [3*BB*60];
__device__ float g_wqkv[(long)LL*QKVN*CC]; // packed [l][n(768)][k(256)]
__device__ float g_bqkv[LL*QKVN];

__device__ __forceinline__ float gelu_exact(float z) {
    return 0.5f * z * (1.0f + erff(z * 0.70710678118654752f));
}

__device__ __forceinline__ unsigned f2tf32(float x) {
    unsigned r;
    asm("cvt.rna.tf32.f32 %0, %1;" : "=r"(r) : "f"(x));
    return r;
}

__device__ __forceinline__ void mma_tf32(float c[4], const unsigned a[4],
                                         unsigned b0, unsigned b1) {
    asm volatile(
        "mma.sync.aligned.m16n8k8.row.col.f32.tf32.tf32.f32 "
        "{%0,%1,%2,%3},{%4,%5,%6,%7},{%8,%9},{%0,%1,%2,%3};"
        : "+f"(c[0]), "+f"(c[1]), "+f"(c[2]), "+f"(c[3])
        : "r"(a[0]), "r"(a[1]), "r"(a[2]), "r"(a[3]), "r"(b0), "r"(b1));
}

// ---------------- fused QKV weight+bias packing ----------------
__global__ void pack_qkv_kernel(const float* __restrict__ Wq, const float* __restrict__ Wk,
                                const float* __restrict__ Wv, const float* __restrict__ bq,
                                const float* __restrict__ bk, const float* __restrict__ bv) {
    const long nw = (long)LL*QKVN*CC;
    long idx = (long)blockIdx.x * blockDim.x + threadIdx.x;
    if (idx < nw) {
        int k = (int)(idx % CC);
        int n = (int)((idx / CC) % QKVN);
        int l = (int)(idx / ((long)CC*QKVN));
        const float* src;
        if      (n < 256) src = &Wq[((long)l*256 + n      )*CC];
        else if (n < 512) src = &Wk[((long)l*256 + n - 256)*CC];
        else              src = &Wv[((long)l*256 + n - 512)*CC];
        g_wqkv[idx] = src[k];
    } else if (idx < nw + (long)LL*QKVN) {
        int r = (int)(idx - nw);
        int n = r % QKVN;
        int l = r / QKVN;
        float v;
        if      (n < 256) v = bq[l*256 + n];
        else if (n < 512) v = bk[l*256 + n - 256];
        else              v = bv[l*256 + n - 512];
        g_bqkv[r] = v;
    }
}

// ---------------- locality MLP ----------------
__global__ void loc1_kernel(const float* __restrict__ p1, const float* __restrict__ p2,
                            const float* __restrict__ p3, const float* __restrict__ W1,
                            const float* __restrict__ b1) {
    int mat = blockIdx.x / BB;
    int b   = blockIdx.x % BB;
    int j   = threadIdx.x;
    if (j >= 60) return;
    const float* p = (mat == 0) ? p1 : (mat == 1) ? p2 : p3;
    float s = b1[j];
    #pragma unroll
    for (int i = 0; i < 30; i++) s += p[b*30 + i] * W1[j*30 + i];
    g_z1[(mat*BB + b)*60 + j] = gelu_exact(s);
}

__global__ void zero_h_kernel() {
    long i = (long)blockIdx.x * blockDim.x + threadIdx.x;
    if (i < (long)BB*TT*TT) g_h[i] = 0.0f;
}

__global__ void loc2_kernel(const float* __restrict__ W2, const float* __restrict__ b2) {
    int idx = blockIdx.x * blockDim.x + threadIdx.x;
    const int total = 3 * BB * 65536;
    if (idx >= total) return;
    int mat = idx / (BB * 65536);
    int rem = idx % (BB * 65536);
    int b   = rem / 65536;
    int o   = rem % 65536;
    const float* z1 = &g_z1[(mat*BB + b)*60];
    const float* wr = &W2[(long)o * 60];
    float s = b2[o];
    #pragma unroll
    for (int j = 0; j < 60; j++) s += z1[j] * wr[j];
    int r = o >> 8, c = o & 255;
    int r0 = (mat == 0) ? 285 : 571;
    int c0 = (mat == 2) ? 286 : 0;
    g_h[((long)b*TT + (r0 + r))*TT + (c0 + c)] = s;
}

// ---------------- embedding ----------------
__global__ void embed_kernel(const float* __restrict__ dc, const float* __restrict__ z,
                             const float* __restrict__ frame, const float* __restrict__ cam,
                             const float* __restrict__ timee) {
    int idx = blockIdx.x * blockDim.x + threadIdx.x;
    if (idx >= MM*CC) return;
    int c = idx % CC;
    int t = (idx / CC) % TT;
    int b = idx / (CC * TT);
    float tok = (t < 572) ? dc[((long)b*572 + t)*CC + c]
                          : z [((long)b*256 + (t - 572))*CC + c];
    float role;
    if      (t < 256) role = frame[(t      )*CC + c];
    else if (t < 286) role = cam  [(t - 256)*CC + c];
    else if (t < 542) role = frame[(t - 286)*CC + c];
    else if (t < 572) role = cam  [(t - 542)*CC + c];
    else              role = frame[(t - 572)*CC + c];
    g_x[idx] = tok + role + timee[t*CC + c];
}

// ---------------- layernorm: single-pass (sum, sumsq) ----------------
__global__ void __launch_bounds__(CC) ln_kernel(const float* __restrict__ x,
                                                const float* __restrict__ w,
                                                const float* __restrict__ b,
                                                float* __restrict__ out) {
    int row = blockIdx.x;
    int tid = threadIdx.x;
    __shared__ float ws1[8], ws2[8];
    __shared__ float mv[2];
    float v = x[(long)row*CC + tid];

    float s1 = v, s2 = v * v;
    #pragma unroll
    for (int o = 16; o; o >>= 1) {
        s1 += __shfl_xor_sync(0xffffffffu, s1, o);
        s2 += __shfl_xor_sync(0xffffffffu, s2, o);
    }
    if ((tid & 31) == 0) { ws1[tid >> 5] = s1; ws2[tid >> 5] = s2; }
    __syncthreads();
    if (tid < 32) {
        float t1 = (tid < 8) ? ws1[tid] : 0.0f;
        float t2 = (tid < 8) ? ws2[tid] : 0.0f;
        #pragma unroll
        for (int o = 4; o; o >>= 1) {
            t1 += __shfl_xor_sync(0xffffffffu, t1, o);
            t2 += __shfl_xor_sync(0xffffffffu, t2, o);
        }
        if (tid == 0) {
            float mean = t1 * (1.0f / CC);
            float var  = t2 * (1.0f / CC) - mean * mean;
            mv[0] = mean;
            mv[1] = rsqrtf(var + 1e-5f);
        }
    }
    __syncthreads();
    out[(long)row*CC + tid] = (v - mv[0]) * mv[1] * w[tid] + b[tid];
}

// ---------------- tensor-core TF32 GEMM (proven 2-stage pipeline, BM templated) ----------------
#define SM_STRIDE 20

__device__ __forceinline__ void cp_async16(unsigned dst, const void* src, int bytes) {
    asm volatile("cp.async.ca.shared.global [%0], [%1], 16, %2;\n"
                 :: "r"(dst), "l"(src), "r"(bytes));
}

template<int BM, bool DO_GELU, bool DO_RES>
__global__ void __launch_bounds__(256)
gemm_tc(const float* __restrict__ A, int lda,
        const float* __restrict__ W,
        const float* __restrict__ bias,
        const float* __restrict__ res,
        float* __restrict__ out, int ldo,
        int M, int N, int K) {
    constexpr int MI = BM / 64;    // 2 (BM=128) or 1 (BM=64)
    __shared__ __align__(16) float As[2][BM*SM_STRIDE];
    __shared__ __align__(16) float Bs[2][64*SM_STRIDE];

    const int tid  = threadIdx.x;
    const int m0   = blockIdx.y * BM;
    const int n0   = blockIdx.x * 64;
    const int warp = tid >> 5, lane = tid & 31;
    const int wm = warp >> 1, wn = warp & 1;
    const int grp = lane >> 2, qd = lane & 3;

    float c[MI][4][4];
    #pragma unroll
    for (int i = 0; i < MI; i++)
        #pragma unroll
        for (int j = 0; j < 4; j++)
            #pragma unroll
            for (int k = 0; k < 4; k++) c[i][j][k] = 0.0f;

    const int a_r0 = tid >> 2,         a_c0 = (tid & 3) << 2;
    const int a_r1 = (tid + 256) >> 2, a_c1 = (tid & 3) << 2;
    const int b_r  = tid >> 2,         b_c  = (tid & 3) << 2;

    unsigned sA[2], sB[2];
    sA[0] = (unsigned)__cvta_generic_to_shared(&As[0][0]);
    sA[1] = (unsigned)__cvta_generic_to_shared(&As[1][0]);
    sB[0] = (unsigned)__cvta_generic_to_shared(&Bs[0][0]);
    sB[1] = (unsigned)__cvta_generic_to_shared(&Bs[1][0]);

    auto load_tiles = [&](int k0, int buf) {
        int m = m0 + a_r0;
        const float* src = A + (long)(m < M ? m : 0) * lda + k0 + a_c0;
        cp_async16(sA[buf] + (a_r0*SM_STRIDE + a_c0)*4, src, m < M ? 16 : 0);
        if (MI == 2) {
            m = m0 + a_r1;
            src = A + (long)(m < M ? m : 0) * lda + k0 + a_c1;
            cp_async16(sA[buf] + (a_r1*SM_STRIDE + a_c1)*4, src, m < M ? 16 : 0);
        }
        const float* srcb = W + (long)(n0 + b_r) * K + k0 + b_c;
        cp_async16(sB[buf] + (b_r*SM_STRIDE + b_c)*4, srcb, 16);
        asm volatile("cp.async.commit_group;\n");
    };

    auto compute = [&](int buf) {
        const float* pa = As[buf];
        const float* pb = Bs[buf];
        #pragma unroll
        for (int ks = 0; ks < 2; ks++) {
            const int kk = ks * 8;
            unsigned a[MI][4], b[4][2];
            #pragma unroll
            for (int mi = 0; mi < MI; mi++) {
                int r = wm*(16*MI) + mi*16 + grp;
                a[mi][0] = f2tf32(pa[(r    )*SM_STRIDE + kk + qd    ]);
                a[mi][1] = f2tf32(pa[(r + 8)*SM_STRIDE + kk + qd    ]);
                a[mi][2] = f2tf32(pa[(r    )*SM_STRIDE + kk + qd + 4]);
                a[mi][3] = f2tf32(pa[(r + 8)*SM_STRIDE + kk + qd + 4]);
            }
            #pragma unroll
            for (int ni = 0; ni < 4; ni++) {
                int n = wn*32 + ni*8 + grp;
                b[ni][0] = f2tf32(pb[n*SM_STRIDE + kk + qd    ]);
                b[ni][1] = f2tf32(pb[n*SM_STRIDE + kk + qd + 4]);
            }
            #pragma unroll
            for (int mi = 0; mi < MI; mi++)
                #pragma unroll
                for (int ni = 0; ni < 4; ni++)
                    mma_tf32(c[mi][ni], a[mi], b[ni][0], b[ni][1]);
        }
    };

    const int nt = K >> 4;
    load_tiles(0, 0);
    for (int t = 0; t < nt; t++) {
        const int buf = t & 1;
        if (t + 1 < nt) {
            load_tiles((t + 1) << 4, 1 - buf);
            asm volatile("cp.async.wait_group 1;\n");
        } else {
            asm volatile("cp.async.wait_group 0;\n");
        }
        __syncthreads();
        compute(buf);
        __syncthreads();
    }

    #pragma unroll
    for (int mi = 0; mi < MI; mi++) {
        #pragma unroll
        for (int ni = 0; ni < 4; ni++) {
            int col = n0 + wn*32 + ni*8 + 2*qd;
            float bsum0 = bias ? bias[col]     : 0.0f;
            float bsum1 = bias ? bias[col + 1] : 0.0f;
            #pragma unroll
            for (int rr = 0; rr < 2; rr++) {
                int row = m0 + wm*(16*MI) + mi*16 + grp + rr*8;
                if (row >= M) continue;
                float v0 = c[mi][ni][rr*2 + 0] + bsum0;
                float v1 = c[mi][ni][rr*2 + 1] + bsum1;
                if (DO_GELU) { v0 = gelu_exact(v0); v1 = gelu_exact(v1); }
                if (DO_RES) {
                    const float2 rv = *reinterpret_cast<const float2*>(&res[(long)row*ldo + col]);
                    v0 += rv.x; v1 += rv.y;
                }
                float2 ov; ov.x = v0; ov.y = v1;
                *reinterpret_cast<float2*>(&out[(long)row*ldo + col]) = ov;
            }
        }
    }
}

// ---------------- tensor-core flash attention (unchanged from R8-passing) ----------------
#define ATQ 64
#define ATK 64
#define QKS 36
#define PSS 68

__global__ void __launch_bounds__(256) attn_kernel(int adaptive) {
    __shared__ __align__(16) float Qs[ATQ*QKS];
    __shared__ __align__(16) float Ks[ATK*QKS];
    __shared__ __align__(16) float Vs[ATK*QKS];
    __shared__ __align__(16) float Ps[ATQ*PSS];
    __shared__ float m_s[ATQ], l_s[ATQ], corr_s[ATQ];

    const int tile = blockIdx.x;
    const int bh   = blockIdx.y;
    const int b = bh >> 3, h = bh & 7;
    const int t = threadIdx.x;
    const int q0 = tile * ATQ;
    const int warp = t >> 5, lane = t & 31;
    const int wm = warp >> 1, wn = warp & 1;
    const int grp = lane >> 2, qd = lane & 3;
    const int rv = t >> 2, sub = t & 3;
    const float scale = 0.1767766952966369f;

    {
        int r = q0 + rv;
        float4 a0 = {0,0,0,0}, a1 = {0,0,0,0};
        if (r < TT) {
            const float4* src = reinterpret_cast<const float4*>(
                &g_qkv[((long)(b*TT + r))*QKVN + h*DHH + sub*8]);
            a0 = src[0]; a1 = src[1];
        }
        float4* qdst = reinterpret_cast<float4*>(&Qs[rv*QKS + sub*8]);
        qdst[0] = a0; qdst[1] = a1;
    }
    if (t < ATQ) { m_s[t] = -1e30f; l_s[t] = 0.0f; }
    __syncthreads();

    unsigned aq[4][4];
    {
        int r0 = wm*16 + grp;
        #pragma unroll
        for (int ks = 0; ks < 4; ks++) {
            int kk = ks*8;
            aq[ks][0] = f2tf32(Qs[(r0    )*QKS + kk + qd    ]);
            aq[ks][1] = f2tf32(Qs[(r0 + 8)*QKS + kk + qd    ]);
            aq[ks][2] = f2tf32(Qs[(r0    )*QKS + kk + qd + 4]);
            aq[ks][3] = f2tf32(Qs[(r0 + 8)*QKS + kk + qd + 4]);
        }
    }

    float co[2][4] = {{0,0,0,0},{0,0,0,0}};

    for (int kt = 0; kt <= tile; kt++) {
        const int k0 = kt * ATK;
        __syncthreads();

        {
            int r = k0 + rv;
            float4 kv0 = {0,0,0,0}, kv1 = {0,0,0,0}, vv0 = {0,0,0,0}, vv1 = {0,0,0,0};
            if (r < TT) {
                const float4* ks = reinterpret_cast<const float4*>(
                    &g_qkv[((long)(b*TT + r))*QKVN + 256 + h*DHH + sub*8]);
                kv0 = ks[0]; kv1 = ks[1];
                const float4* vs = reinterpret_cast<const float4*>(
                    &g_qkv[((long)(b*TT + r))*QKVN + 512 + h*DHH + sub*8]);
                vv0 = vs[0]; vv1 = vs[1];
            }
            float4* kd = reinterpret_cast<float4*>(&Ks[rv*QKS + sub*8]);
            kd[0] = kv0; kd[1] = kv1;
            float4* vd = reinterpret_cast<float4*>(&Vs[rv*QKS + sub*8]);
            vd[0] = vv0; vd[1] = vv1;
        }
        __syncthreads();

        float cs[4][4];
        #pragma unroll
        for (int ni = 0; ni < 4; ni++)
            #pragma unroll
            for (int j = 0; j < 4; j++) cs[ni][j] = 0.0f;
        #pragma unroll
        for (int ks = 0; ks < 4; ks++) {
            int kk = ks*8;
            unsigned bf[4][2];
            #pragma unroll
            for (int ni = 0; ni < 4; ni++) {
                int kn = wn*32 + ni*8 + grp;
                bf[ni][0] = f2tf32(Ks[kn*QKS + kk + qd    ]);
                bf[ni][1] = f2tf32(Ks[kn*QKS + kk + qd + 4]);
            }
            #pragma unroll
            for (int ni = 0; ni < 4; ni++)
                mma_tf32(cs[ni], aq[ks], bf[ni][0], bf[ni][1]);
        }

        const int r0 = wm*16 + grp;
        #pragma unroll
        for (int rr = 0; rr < 2; rr++) {
            int rl = r0 + rr*8;
            int q  = q0 + rl;
            bool qvalid = (q < TT);
            #pragma unroll
            for (int ni = 0; ni < 4; ni++) {
                int cl = wn*32 + ni*8 + 2*qd;
                int kc = k0 + cl;
                float v0, v1;
                if (kc > q || !qvalid) v0 = -1e30f;
                else {
                    float bias = adaptive ? g_h[((long)b*TT + q)*TT + kc] : 0.0f;
                    v0 = cs[ni][rr*2 + 0]*scale + bias;
                }
                if (kc + 1 > q || !qvalid) v1 = -1e30f;
                else {
                    float bias = adaptive ? g_h[((long)b*TT + q)*TT + kc + 1] : 0.0f;
                    v1 = cs[ni][rr*2 + 1]*scale + bias;
                }
                float2 sv; sv.x = v0; sv.y = v1;
                *reinterpret_cast<float2*>(&Ps[rl*PSS + cl]) = sv;
            }
        }
        __syncthreads();

        {
            float* pr = &Ps[rv*PSS + sub*16];
            float tmax = -1e30f;
            #pragma unroll
            for (int j = 0; j < 16; j++) tmax = fmaxf(tmax, pr[j]);
            tmax = fmaxf(tmax, __shfl_xor_sync(0xffffffffu, tmax, 1));
            tmax = fmaxf(tmax, __shfl_xor_sync(0xffffffffu, tmax, 2));
            float m_old = m_s[rv];
            float m_new = fmaxf(m_old, tmax);
            float tsum = 0.0f;
            #pragma unroll
            for (int j = 0; j < 16; j++) {
                float p = __expf(pr[j] - m_new);
                pr[j] = p;
                tsum += p;
            }
            tsum += __shfl_xor_sync(0xffffffffu, tsum, 1);
            tsum += __shfl_xor_sync(0xffffffffu, tsum, 2);
            if (sub == 0) {
                float corr = __expf(m_old - m_new);
                corr_s[rv] = corr;
                l_s[rv]    = l_s[rv]*corr + tsum;
                m_s[rv]    = m_new;
            }
        }
        __syncthreads();

        {
            float c0f = corr_s[r0];
            float c1f = corr_s[r0 + 8];
            #pragma unroll
            for (int nj = 0; nj < 2; nj++) {
                co[nj][0] *= c0f; co[nj][1] *= c0f;
                co[nj][2] *= c1f; co[nj][3] *= c1f;
            }
            #pragma unroll
            for (int ks = 0; ks < 8; ks++) {
                int kk = ks*8;
                unsigned ap[4];
                ap[0] = f2tf32(Ps[(r0    )*PSS + kk + qd    ]);
                ap[1] = f2tf32(Ps[(r0 + 8)*PSS + kk + qd    ]);
                ap[2] = f2tf32(Ps[(r0    )*PSS + kk + qd + 4]);
                ap[3] = f2tf32(Ps[(r0 + 8)*PSS + kk + qd + 4]);
                #pragma unroll
                for (int nj = 0; nj < 2; nj++) {
                    int nc = wn*16 + nj*8 + grp;
                    unsigned b0 = f2tf32(Vs[(kk + qd    )*QKS + nc]);
                    unsigned b1 = f2tf32(Vs[(kk + qd + 4)*QKS + nc]);
                    mma_tf32(co[nj], ap, b0, b1);
                }
            }
        }
    }

    {
        const int r0 = wm*16 + grp;
        int qa = q0 + r0, qb = q0 + r0 + 8;
        float inva = (qa < TT) ? 1.0f / l_s[r0]     : 0.0f;
        float invb = (qb < TT) ? 1.0f / l_s[r0 + 8] : 0.0f;
        #pragma unroll
        for (int nj = 0; nj < 2; nj++) {
            int col = wn*16 + nj*8 + 2*qd;
            if (qa < TT) {
                float2 ov; ov.x = co[nj][0]*inva; ov.y = co[nj][1]*inva;
                *reinterpret_cast<float2*>(&g_y[((long)(b*TT + qa))*CC + h*DHH + col]) = ov;
            }
            if (qb < TT) {
                float2 ov; ov.x = co[nj][2]*invb; ov.y = co[nj][3]*invb;
                *reinterpret_cast<float2*>(&g_y[((long)(b*TT + qb))*CC + h*DHH + col]) = ov;
            }
        }
    }
}

// ---------------- launch ----------------
extern "C" void kernel_launch(void* const* d_in, const int* in_sizes, int n_in,
                              void* d_out, int out_size) {
    const float* dc      = (const float*)d_in[0];
    const float* z       = (const float*)d_in[1];
    const float* p1      = (const float*)d_in[2];
    const float* p2      = (const float*)d_in[3];
    const float* p3      = (const float*)d_in[4];
    const float* frame   = (const float*)d_in[5];
    const float* cam     = (const float*)d_in[6];
    const float* timee   = (const float*)d_in[7];
    const float* locW1   = (const float*)d_in[8];
    const float* locb1   = (const float*)d_in[9];
    const float* locW2   = (const float*)d_in[10];
    const float* locb2   = (const float*)d_in[11];
    const float* ln1w    = (const float*)d_in[12];
    const float* ln1b    = (const float*)d_in[13];
    const float* Wq      = (const float*)d_in[14];
    const float* bq      = (const float*)d_in[15];
    const float* Wk      = (const float*)d_in[16];
    const float* bk      = (const float*)d_in[17];
    const float* Wv      = (const float*)d_in[18];
    const float* bv      = (const float*)d_in[19];
    const float* Wo      = (const float*)d_in[20];
    const float* bo      = (const float*)d_in[21];
    const float* ln2w    = (const float*)d_in[22];
    const float* ln2b    = (const float*)d_in[23];
    const float* W1      = (const float*)d_in[24];
    const float* b1      = (const float*)d_in[25];
    const float* W2      = (const float*)d_in[26];
    const float* b2      = (const float*)d_in[27];
    const float* lnfw    = (const float*)d_in[28];
    const float* lnfb    = (const float*)d_in[29];
    const float* headW   = (const float*)d_in[30];

    float *xp, *xnp, *qkvp, *yp, *ffnp, *wqkvp, *bqkvp;
    cudaGetSymbolAddress((void**)&xp,    g_x);
    cudaGetSymbolAddress((void**)&xnp,   g_xn);
    cudaGetSymbolAddress((void**)&qkvp,  g_qkv);
    cudaGetSymbolAddress((void**)&yp,    g_y);
    cudaGetSymbolAddress((void**)&ffnp,  g_ffn);
    cudaGetSymbolAddress((void**)&wqkvp, g_wqkv);
    cudaGetSymbolAddress((void**)&bqkvp, g_bqkv);

    const int MB128 = (MM + 127) / 128;  // 26
    const int MB64  = (MM + 63) / 64;    // 52
    dim3 g_qkvg(QKVN/64, MB128);
    dim3 g_cc(CC/64, MB64);              // BM=64 variant: 4 x 52 = 208 blocks
    dim3 g_ff(FF/64, MB128);
    dim3 attn_grid((TT + ATQ - 1)/ATQ, BB*HH);

    {
        long np = (long)LL*QKVN*CC + (long)LL*QKVN;
        pack_qkv_kernel<<<(int)((np + 255) / 256), 256>>>(Wq, Wk, Wv, bq, bk, bv);
    }
    embed_kernel<<<(MM*CC + 255) / 256, 256>>>(dc, z, frame, cam, timee);

    for (int l = 0; l < LL; l++) {
        ln_kernel<<<MM, CC>>>(xp, ln1w + l*CC, ln1b + l*CC, xnp);

        gemm_tc<128,false,false><<<g_qkvg, 256>>>(xnp, CC, wqkvp + (long)l*QKVN*CC,
                                                  bqkvp + l*QKVN, nullptr, qkvp, QKVN,
                                                  MM, QKVN, CC);

        if (l == 0) {
            long nh = (long)BB*TT*TT;
            zero_h_kernel<<<(int)((nh + 255) / 256), 256>>>();
            loc1_kernel<<<3*BB, 64>>>(p1, p2, p3, locW1, locb1);
            loc2_kernel<<<(3*BB*65536 + 127) / 128, 128>>>(locW2, locb2);
        }

        attn_kernel<<<attn_grid, 256>>>((l % 2 == 0) ? 1 : 0);

        gemm_tc<64,false,true><<<g_cc, 256>>>(yp, CC, Wo + (long)l*CC*CC, bo + l*CC,
                                              xp, xp, CC, MM, CC, CC);

        ln_kernel<<<MM, CC>>>(xp, ln2w + l*CC, ln2b + l*CC, xnp);

        gemm_tc<128,true,false><<<g_ff, 256>>>(xnp, CC, W1 + (long)l*FF*CC, b1 + (long)l*FF,
                                               nullptr, ffnp, FF, MM, FF, CC);
        gemm_tc<64,false,true><<<g_cc, 256>>>(ffnp, FF, W2 + (long)l*CC*FF, b2 + l*CC,
                                              xp, xp, CC, MM, CC, FF);
    }

    ln_kernel<<<MM, CC>>>(xp, lnfw, lnfb, xnp);

    dim3 g_head(VOC/64, MB128);
    gemm_tc<128,false,false><<<g_head, 256>>>(xnp, CC, headW, nullptr, nullptr,
                                              (float*)d_out, VOC, MM, VOC, CC);
}

// round 12
// speedup vs baseline: 1.0024x; 1.0024x over previous
#include <cuda_runtime.h>
#include <math.h>

// ---------------- problem constants ----------------
#define BB   4
#define TT   827
#define CC   256
#define HH   8
#define DHH  32
#define LL   12
#define FF   1024            // 4*C
#define MM   (BB*TT)         // 3308 rows
#define VOC  16384
#define QKVN 768

// ---------------- scratch (device globals; no allocs allowed) ----------------
__device__ float g_x   [MM*CC];
__device__ float g_xn  [MM*CC];
__device__ float g_qkv [MM*QKVN];
__device__ float g_y   [MM*CC];
__device__ float g_ffn [MM*FF];
__device__ float g_h   [(long)BB*TT*TT];   // additive attention bias (even layers)
__device__ float g_z1  [3*BB*60];
__device__ float g_wqkv[(long)LL*QKVN*CC]; // packed [l][n(768)][k(256)]
__device__ float g_bqkv[LL*QKVN];

__device__ __forceinline__ float gelu_exact(float z) {
    return 0.5f * z * (1.0f + erff(z * 0.70710678118654752f));
}

__device__ __forceinline__ unsigned f2tf32(float x) {
    unsigned r;
    asm("cvt.rna.tf32.f32 %0, %1;" : "=r"(r) : "f"(x));
    return r;
}

__device__ __forceinline__ void mma_tf32(float c[4], const unsigned a[4],
                                         unsigned b0, unsigned b1) {
    asm volatile(
        "mma.sync.aligned.m16n8k8.row.col.f32.tf32.tf32.f32 "
        "{%0,%1,%2,%3},{%4,%5,%6,%7},{%8,%9},{%0,%1,%2,%3};"
        : "+f"(c[0]), "+f"(c[1]), "+f"(c[2]), "+f"(c[3])
        : "r"(a[0]), "r"(a[1]), "r"(a[2]), "r"(a[3]), "r"(b0), "r"(b1));
}

// ---------------- fused QKV weight+bias packing ----------------
__global__ void pack_qkv_kernel(const float* __restrict__ Wq, const float* __restrict__ Wk,
                                const float* __restrict__ Wv, const float* __restrict__ bq,
                                const float* __restrict__ bk, const float* __restrict__ bv) {
    const long nw = (long)LL*QKVN*CC;
    long idx = (long)blockIdx.x * blockDim.x + threadIdx.x;
    if (idx < nw) {
        int k = (int)(idx % CC);
        int n = (int)((idx / CC) % QKVN);
        int l = (int)(idx / ((long)CC*QKVN));
        const float* src;
        if      (n < 256) src = &Wq[((long)l*256 + n      )*CC];
        else if (n < 512) src = &Wk[((long)l*256 + n - 256)*CC];
        else              src = &Wv[((long)l*256 + n - 512)*CC];
        g_wqkv[idx] = src[k];
    } else if (idx < nw + (long)LL*QKVN) {
        int r = (int)(idx - nw);
        int n = r % QKVN;
        int l = r / QKVN;
        float v;
        if      (n < 256) v = bq[l*256 + n];
        else if (n < 512) v = bk[l*256 + n - 256];
        else              v = bv[l*256 + n - 512];
        g_bqkv[r] = v;
    }
}

// ---------------- locality MLP ----------------
__global__ void loc1_kernel(const float* __restrict__ p1, const float* __restrict__ p2,
                            const float* __restrict__ p3, const float* __restrict__ W1,
                            const float* __restrict__ b1) {
    int mat = blockIdx.x / BB;
    int b   = blockIdx.x % BB;
    int j   = threadIdx.x;
    if (j >= 60) return;
    const float* p = (mat == 0) ? p1 : (mat == 1) ? p2 : p3;
    float s = b1[j];
    #pragma unroll
    for (int i = 0; i < 30; i++) s += p[b*30 + i] * W1[j*30 + i];
    g_z1[(mat*BB + b)*60 + j] = gelu_exact(s);
}

__global__ void zero_h_kernel() {
    long i = (long)blockIdx.x * blockDim.x + threadIdx.x;
    if (i < (long)BB*TT*TT) g_h[i] = 0.0f;
}

__global__ void loc2_kernel(const float* __restrict__ W2, const float* __restrict__ b2) {
    int idx = blockIdx.x * blockDim.x + threadIdx.x;
    const int total = 3 * BB * 65536;
    if (idx >= total) return;
    int mat = idx / (BB * 65536);
    int rem = idx % (BB * 65536);
    int b   = rem / 65536;
    int o   = rem % 65536;
    const float* z1 = &g_z1[(mat*BB + b)*60];
    const float* wr = &W2[(long)o * 60];
    float s = b2[o];
    #pragma unroll
    for (int j = 0; j < 60; j++) s += z1[j] * wr[j];
    int r = o >> 8, c = o & 255;
    int r0 = (mat == 0) ? 285 : 571;
    int c0 = (mat == 2) ? 286 : 0;
    g_h[((long)b*TT + (r0 + r))*TT + (c0 + c)] = s;
}

// ---------------- embedding ----------------
__global__ void embed_kernel(const float* __restrict__ dc, const float* __restrict__ z,
                             const float* __restrict__ frame, const float* __restrict__ cam,
                             const float* __restrict__ timee) {
    int idx = blockIdx.x * blockDim.x + threadIdx.x;
    if (idx >= MM*CC) return;
    int c = idx % CC;
    int t = (idx / CC) % TT;
    int b = idx / (CC * TT);
    float tok = (t < 572) ? dc[((long)b*572 + t)*CC + c]
                          : z [((long)b*256 + (t - 572))*CC + c];
    float role;
    if      (t < 256) role = frame[(t      )*CC + c];
    else if (t < 286) role = cam  [(t - 256)*CC + c];
    else if (t < 542) role = frame[(t - 286)*CC + c];
    else if (t < 572) role = cam  [(t - 542)*CC + c];
    else              role = frame[(t - 572)*CC + c];
    g_x[idx] = tok + role + timee[t*CC + c];
}

// ---------------- layernorm: single-pass (sum, sumsq) ----------------
__global__ void __launch_bounds__(CC) ln_kernel(const float* __restrict__ x,
                                                const float* __restrict__ w,
                                                const float* __restrict__ b,
                                                float* __restrict__ out) {
    int row = blockIdx.x;
    int tid = threadIdx.x;
    __shared__ float ws1[8], ws2[8];
    __shared__ float mv[2];
    float v = x[(long)row*CC + tid];

    float s1 = v, s2 = v * v;
    #pragma unroll
    for (int o = 16; o; o >>= 1) {
        s1 += __shfl_xor_sync(0xffffffffu, s1, o);
        s2 += __shfl_xor_sync(0xffffffffu, s2, o);
    }
    if ((tid & 31) == 0) { ws1[tid >> 5] = s1; ws2[tid >> 5] = s2; }
    __syncthreads();
    if (tid < 32) {
        float t1 = (tid < 8) ? ws1[tid] : 0.0f;
        float t2 = (tid < 8) ? ws2[tid] : 0.0f;
        #pragma unroll
        for (int o = 4; o; o >>= 1) {
            t1 += __shfl_xor_sync(0xffffffffu, t1, o);
            t2 += __shfl_xor_sync(0xffffffffu, t2, o);
        }
        if (tid == 0) {
            float mean = t1 * (1.0f / CC);
            float var  = t2 * (1.0f / CC) - mean * mean;
            mv[0] = mean;
            mv[1] = rsqrtf(var + 1e-5f);
        }
    }
    __syncthreads();
    out[(long)row*CC + tid] = (v - mv[0]) * mv[1] * w[tid] + b[tid];
}

// ---------------- tensor-core TF32 GEMM (proven 2-stage pipeline, BM templated) ----------------
#define SM_STRIDE 20

__device__ __forceinline__ void cp_async16(unsigned dst, const void* src, int bytes) {
    asm volatile("cp.async.ca.shared.global [%0], [%1], 16, %2;\n"
                 :: "r"(dst), "l"(src), "r"(bytes));
}

template<int BM, bool DO_GELU, bool DO_RES>
__global__ void __launch_bounds__(256)
gemm_tc(const float* __restrict__ A, int lda,
        const float* __restrict__ W,
        const float* __restrict__ bias,
        const float* __restrict__ res,
        float* __restrict__ out, int ldo,
        int M, int N, int K) {
    constexpr int MI = BM / 64;    // 2 (BM=128) or 1 (BM=64)
    __shared__ __align__(16) float As[2][BM*SM_STRIDE];
    __shared__ __align__(16) float Bs[2][64*SM_STRIDE];

    const int tid  = threadIdx.x;
    const int m0   = blockIdx.y * BM;
    const int n0   = blockIdx.x * 64;
    const int warp = tid >> 5, lane = tid & 31;
    const int wm = warp >> 1, wn = warp & 1;
    const int grp = lane >> 2, qd = lane & 3;

    float c[MI][4][4];
    #pragma unroll
    for (int i = 0; i < MI; i++)
        #pragma unroll
        for (int j = 0; j < 4; j++)
            #pragma unroll
            for (int k = 0; k < 4; k++) c[i][j][k] = 0.0f;

    const int a_r0 = tid >> 2,         a_c0 = (tid & 3) << 2;
    const int a_r1 = (tid + 256) >> 2, a_c1 = (tid & 3) << 2;
    const int b_r  = tid >> 2,         b_c  = (tid & 3) << 2;

    unsigned sA[2], sB[2];
    sA[0] = (unsigned)__cvta_generic_to_shared(&As[0][0]);
    sA[1] = (unsigned)__cvta_generic_to_shared(&As[1][0]);
    sB[0] = (unsigned)__cvta_generic_to_shared(&Bs[0][0]);
    sB[1] = (unsigned)__cvta_generic_to_shared(&Bs[1][0]);

    auto load_tiles = [&](int k0, int buf) {
        int m = m0 + a_r0;
        const float* src = A + (long)(m < M ? m : 0) * lda + k0 + a_c0;
        cp_async16(sA[buf] + (a_r0*SM_STRIDE + a_c0)*4, src, m < M ? 16 : 0);
        if (MI == 2) {
            m = m0 + a_r1;
            src = A + (long)(m < M ? m : 0) * lda + k0 + a_c1;
            cp_async16(sA[buf] + (a_r1*SM_STRIDE + a_c1)*4, src, m < M ? 16 : 0);
        }
        const float* srcb = W + (long)(n0 + b_r) * K + k0 + b_c;
        cp_async16(sB[buf] + (b_r*SM_STRIDE + b_c)*4, srcb, 16);
        asm volatile("cp.async.commit_group;\n");
    };

    auto compute = [&](int buf) {
        const float* pa = As[buf];
        const float* pb = Bs[buf];
        #pragma unroll
        for (int ks = 0; ks < 2; ks++) {
            const int kk = ks * 8;
            unsigned a[MI][4], b[4][2];
            #pragma unroll
            for (int mi = 0; mi < MI; mi++) {
                int r = wm*(16*MI) + mi*16 + grp;
                a[mi][0] = f2tf32(pa[(r    )*SM_STRIDE + kk + qd    ]);
                a[mi][1] = f2tf32(pa[(r + 8)*SM_STRIDE + kk + qd    ]);
                a[mi][2] = f2tf32(pa[(r    )*SM_STRIDE + kk + qd + 4]);
                a[mi][3] = f2tf32(pa[(r + 8)*SM_STRIDE + kk + qd + 4]);
            }
            #pragma unroll
            for (int ni = 0; ni < 4; ni++) {
                int n = wn*32 + ni*8 + grp;
                b[ni][0] = f2tf32(pb[n*SM_STRIDE + kk + qd    ]);
                b[ni][1] = f2tf32(pb[n*SM_STRIDE + kk + qd + 4]);
            }
            #pragma unroll
            for (int mi = 0; mi < MI; mi++)
                #pragma unroll
                for (int ni = 0; ni < 4; ni++)
                    mma_tf32(c[mi][ni], a[mi], b[ni][0], b[ni][1]);
        }
    };

    const int nt = K >> 4;
    load_tiles(0, 0);
    for (int t = 0; t < nt; t++) {
        const int buf = t & 1;
        if (t + 1 < nt) {
            load_tiles((t + 1) << 4, 1 - buf);
            asm volatile("cp.async.wait_group 1;\n");
        } else {
            asm volatile("cp.async.wait_group 0;\n");
        }
        __syncthreads();
        compute(buf);
        __syncthreads();
    }

    #pragma unroll
    for (int mi = 0; mi < MI; mi++) {
        #pragma unroll
        for (int ni = 0; ni < 4; ni++) {
            int col = n0 + wn*32 + ni*8 + 2*qd;
            float bsum0 = bias ? bias[col]     : 0.0f;
            float bsum1 = bias ? bias[col + 1] : 0.0f;
            #pragma unroll
            for (int rr = 0; rr < 2; rr++) {
                int row = m0 + wm*(16*MI) + mi*16 + grp + rr*8;
                if (row >= M) continue;
                float v0 = c[mi][ni][rr*2 + 0] + bsum0;
                float v1 = c[mi][ni][rr*2 + 1] + bsum1;
                if (DO_GELU) { v0 = gelu_exact(v0); v1 = gelu_exact(v1); }
                if (DO_RES) {
                    const float2 rv = *reinterpret_cast<const float2*>(&res[(long)row*ldo + col]);
                    v0 += rv.x; v1 += rv.y;
                }
                float2 ov; ov.x = v0; ov.y = v1;
                *reinterpret_cast<float2*>(&out[(long)row*ldo + col]) = ov;
            }
        }
    }
}

// ---------------- tensor-core flash attention (unchanged from R8-passing) ----------------
#define ATQ 64
#define ATK 64
#define QKS 36
#define PSS 68

__global__ void __launch_bounds__(256) attn_kernel(int adaptive) {
    __shared__ __align__(16) float Qs[ATQ*QKS];
    __shared__ __align__(16) float Ks[ATK*QKS];
    __shared__ __align__(16) float Vs[ATK*QKS];
    __shared__ __align__(16) float Ps[ATQ*PSS];
    __shared__ float m_s[ATQ], l_s[ATQ], corr_s[ATQ];

    const int tile = blockIdx.x;
    const int bh   = blockIdx.y;
    const int b = bh >> 3, h = bh & 7;
    const int t = threadIdx.x;
    const int q0 = tile * ATQ;
    const int warp = t >> 5, lane = t & 31;
    const int wm = warp >> 1, wn = warp & 1;
    const int grp = lane >> 2, qd = lane & 3;
    const int rv = t >> 2, sub = t & 3;
    const float scale = 0.1767766952966369f;

    {
        int r = q0 + rv;
        float4 a0 = {0,0,0,0}, a1 = {0,0,0,0};
        if (r < TT) {
            const float4* src = reinterpret_cast<const float4*>(
                &g_qkv[((long)(b*TT + r))*QKVN + h*DHH + sub*8]);
            a0 = src[0]; a1 = src[1];
        }
        float4* qdst = reinterpret_cast<float4*>(&Qs[rv*QKS + sub*8]);
        qdst[0] = a0; qdst[1] = a1;
    }
    if (t < ATQ) { m_s[t] = -1e30f; l_s[t] = 0.0f; }
    __syncthreads();

    unsigned aq[4][4];
    {
        int r0 = wm*16 + grp;
        #pragma unroll
        for (int ks = 0; ks < 4; ks++) {
            int kk = ks*8;
            aq[ks][0] = f2tf32(Qs[(r0    )*QKS + kk + qd    ]);
            aq[ks][1] = f2tf32(Qs[(r0 + 8)*QKS + kk + qd    ]);
            aq[ks][2] = f2tf32(Qs[(r0    )*QKS + kk + qd + 4]);
            aq[ks][3] = f2tf32(Qs[(r0 + 8)*QKS + kk + qd + 4]);
        }
    }

    float co[2][4] = {{0,0,0,0},{0,0,0,0}};

    for (int kt = 0; kt <= tile; kt++) {
        const int k0 = kt * ATK;
        __syncthreads();

        {
            int r = k0 + rv;
            float4 kv0 = {0,0,0,0}, kv1 = {0,0,0,0}, vv0 = {0,0,0,0}, vv1 = {0,0,0,0};
            if (r < TT) {
                const float4* ks = reinterpret_cast<const float4*>(
                    &g_qkv[((long)(b*TT + r))*QKVN + 256 + h*DHH + sub*8]);
                kv0 = ks[0]; kv1 = ks[1];
                const float4* vs = reinterpret_cast<const float4*>(
                    &g_qkv[((long)(b*TT + r))*QKVN + 512 + h*DHH + sub*8]);
                vv0 = vs[0]; vv1 = vs[1];
            }
            float4* kd = reinterpret_cast<float4*>(&Ks[rv*QKS + sub*8]);
            kd[0] = kv0; kd[1] = kv1;
            float4* vd = reinterpret_cast<float4*>(&Vs[rv*QKS + sub*8]);
            vd[0] = vv0; vd[1] = vv1;
        }
        __syncthreads();

        float cs[4][4];
        #pragma unroll
        for (int ni = 0; ni < 4; ni++)
            #pragma unroll
            for (int j = 0; j < 4; j++) cs[ni][j] = 0.0f;
        #pragma unroll
        for (int ks = 0; ks < 4; ks++) {
            int kk = ks*8;
            unsigned bf[4][2];
            #pragma unroll
            for (int ni = 0; ni < 4; ni++) {
                int kn = wn*32 + ni*8 + grp;
                bf[ni][0] = f2tf32(Ks[kn*QKS + kk + qd    ]);
                bf[ni][1] = f2tf32(Ks[kn*QKS + kk + qd + 4]);
            }
            #pragma unroll
            for (int ni = 0; ni < 4; ni++)
                mma_tf32(cs[ni], aq[ks], bf[ni][0], bf[ni][1]);
        }

        const int r0 = wm*16 + grp;
        #pragma unroll
        for (int rr = 0; rr < 2; rr++) {
            int rl = r0 + rr*8;
            int q  = q0 + rl;
            bool qvalid = (q < TT);
            #pragma unroll
            for (int ni = 0; ni < 4; ni++) {
                int cl = wn*32 + ni*8 + 2*qd;
                int kc = k0 + cl;
                float v0, v1;
                if (kc > q || !qvalid) v0 = -1e30f;
                else {
                    float bias = adaptive ? g_h[((long)b*TT + q)*TT + kc] : 0.0f;
                    v0 = cs[ni][rr*2 + 0]*scale + bias;
                }
                if (kc + 1 > q || !qvalid) v1 = -1e30f;
                else {
                    float bias = adaptive ? g_h[((long)b*TT + q)*TT + kc + 1] : 0.0f;
                    v1 = cs[ni][rr*2 + 1]*scale + bias;
                }
                float2 sv; sv.x = v0; sv.y = v1;
                *reinterpret_cast<float2*>(&Ps[rl*PSS + cl]) = sv;
            }
        }
        __syncthreads();

        {
            float* pr = &Ps[rv*PSS + sub*16];
            float tmax = -1e30f;
            #pragma unroll
            for (int j = 0; j < 16; j++) tmax = fmaxf(tmax, pr[j]);
            tmax = fmaxf(tmax, __shfl_xor_sync(0xffffffffu, tmax, 1));
            tmax = fmaxf(tmax, __shfl_xor_sync(0xffffffffu, tmax, 2));
            float m_old = m_s[rv];
            float m_new = fmaxf(m_old, tmax);
            float tsum = 0.0f;
            #pragma unroll
            for (int j = 0; j < 16; j++) {
                float p = __expf(pr[j] - m_new);
                pr[j] = p;
                tsum += p;
            }
            tsum += __shfl_xor_sync(0xffffffffu, tsum, 1);
            tsum += __shfl_xor_sync(0xffffffffu, tsum, 2);
            if (sub == 0) {
                float corr = __expf(m_old - m_new);
                corr_s[rv] = corr;
                l_s[rv]    = l_s[rv]*corr + tsum;
                m_s[rv]    = m_new;
            }
        }
        __syncthreads();

        {
            float c0f = corr_s[r0];
            float c1f = corr_s[r0 + 8];
            #pragma unroll
            for (int nj = 0; nj < 2; nj++) {
                co[nj][0] *= c0f; co[nj][1] *= c0f;
                co[nj][2] *= c1f; co[nj][3] *= c1f;
            }
            #pragma unroll
            for (int ks = 0; ks < 8; ks++) {
                int kk = ks*8;
                unsigned ap[4];
                ap[0] = f2tf32(Ps[(r0    )*PSS + kk + qd    ]);
                ap[1] = f2tf32(Ps[(r0 + 8)*PSS + kk + qd    ]);
                ap[2] = f2tf32(Ps[(r0    )*PSS + kk + qd + 4]);
                ap[3] = f2tf32(Ps[(r0 + 8)*PSS + kk + qd + 4]);
                #pragma unroll
                for (int nj = 0; nj < 2; nj++) {
                    int nc = wn*16 + nj*8 + grp;
                    unsigned b0 = f2tf32(Vs[(kk + qd    )*QKS + nc]);
                    unsigned b1 = f2tf32(Vs[(kk + qd + 4)*QKS + nc]);
                    mma_tf32(co[nj], ap, b0, b1);
                }
            }
        }
    }

    {
        const int r0 = wm*16 + grp;
        int qa = q0 + r0, qb = q0 + r0 + 8;
        float inva = (qa < TT) ? 1.0f / l_s[r0]     : 0.0f;
        float invb = (qb < TT) ? 1.0f / l_s[r0 + 8] : 0.0f;
        #pragma unroll
        for (int nj = 0; nj < 2; nj++) {
            int col = wn*16 + nj*8 + 2*qd;
            if (qa < TT) {
                float2 ov; ov.x = co[nj][0]*inva; ov.y = co[nj][1]*inva;
                *reinterpret_cast<float2*>(&g_y[((long)(b*TT + qa))*CC + h*DHH + col]) = ov;
            }
            if (qb < TT) {
                float2 ov; ov.x = co[nj][2]*invb; ov.y = co[nj][3]*invb;
                *reinterpret_cast<float2*>(&g_y[((long)(b*TT + qb))*CC + h*DHH + col]) = ov;
            }
        }
    }
}

// ---------------- launch ----------------
extern "C" void kernel_launch(void* const* d_in, const int* in_sizes, int n_in,
                              void* d_out, int out_size) {
    const float* dc      = (const float*)d_in[0];
    const float* z       = (const float*)d_in[1];
    const float* p1      = (const float*)d_in[2];
    const float* p2      = (const float*)d_in[3];
    const float* p3      = (const float*)d_in[4];
    const float* frame   = (const float*)d_in[5];
    const float* cam     = (const float*)d_in[6];
    const float* timee   = (const float*)d_in[7];
    const float* locW1   = (const float*)d_in[8];
    const float* locb1   = (const float*)d_in[9];
    const float* locW2   = (const float*)d_in[10];
    const float* locb2   = (const float*)d_in[11];
    const float* ln1w    = (const float*)d_in[12];
    const float* ln1b    = (const float*)d_in[13];
    const float* Wq      = (const float*)d_in[14];
    const float* bq      = (const float*)d_in[15];
    const float* Wk      = (const float*)d_in[16];
    const float* bk      = (const float*)d_in[17];
    const float* Wv      = (const float*)d_in[18];
    const float* bv      = (const float*)d_in[19];
    const float* Wo      = (const float*)d_in[20];
    const float* bo      = (const float*)d_in[21];
    const float* ln2w    = (const float*)d_in[22];
    const float* ln2b    = (const float*)d_in[23];
    const float* W1      = (const float*)d_in[24];
    const float* b1      = (const float*)d_in[25];
    const float* W2      = (const float*)d_in[26];
    const float* b2      = (const float*)d_in[27];
    const float* lnfw    = (const float*)d_in[28];
    const float* lnfb    = (const float*)d_in[29];
    const float* headW   = (const float*)d_in[30];

    float *xp, *xnp, *qkvp, *yp, *ffnp, *wqkvp, *bqkvp;
    cudaGetSymbolAddress((void**)&xp,    g_x);
    cudaGetSymbolAddress((void**)&xnp,   g_xn);
    cudaGetSymbolAddress((void**)&qkvp,  g_qkv);
    cudaGetSymbolAddress((void**)&yp,    g_y);
    cudaGetSymbolAddress((void**)&ffnp,  g_ffn);
    cudaGetSymbolAddress((void**)&wqkvp, g_wqkv);
    cudaGetSymbolAddress((void**)&bqkvp, g_bqkv);

    const int MB128 = (MM + 127) / 128;  // 26
    const int MB64  = (MM + 63) / 64;    // 52
    dim3 g_qkvg(QKVN/64, MB128);
    dim3 g_cc(CC/64, MB64);              // BM=64 variant: 4 x 52 = 208 blocks
    dim3 g_ff(FF/64, MB128);
    dim3 attn_grid((TT + ATQ - 1)/ATQ, BB*HH);

    {
        long np = (long)LL*QKVN*CC + (long)LL*QKVN;
        pack_qkv_kernel<<<(int)((np + 255) / 256), 256>>>(Wq, Wk, Wv, bq, bk, bv);
    }
    embed_kernel<<<(MM*CC + 255) / 256, 256>>>(dc, z, frame, cam, timee);

    for (int l = 0; l < LL; l++) {
        ln_kernel<<<MM, CC>>>(xp, ln1w + l*CC, ln1b + l*CC, xnp);

        gemm_tc<128,false,false><<<g_qkvg, 256>>>(xnp, CC, wqkvp + (long)l*QKVN*CC,
                                                  bqkvp + l*QKVN, nullptr, qkvp, QKVN,
                                                  MM, QKVN, CC);

        if (l == 0) {
            long nh = (long)BB*TT*TT;
            zero_h_kernel<<<(int)((nh + 255) / 256), 256>>>();
            loc1_kernel<<<3*BB, 64>>>(p1, p2, p3, locW1, locb1);
            loc2_kernel<<<(3*BB*65536 + 127) / 128, 128>>>(locW2, locb2);
        }

        attn_kernel<<<attn_grid, 256>>>((l % 2 == 0) ? 1 : 0);

        gemm_tc<64,false,true><<<g_cc, 256>>>(yp, CC, Wo + (long)l*CC*CC, bo + l*CC,
                                              xp, xp, CC, MM, CC, CC);

        ln_kernel<<<MM, CC>>>(xp, ln2w + l*CC, ln2b + l*CC, xnp);

        gemm_tc<128,true,false><<<g_ff, 256>>>(xnp, CC, W1 + (long)l*FF*CC, b1 + (long)l*FF,
                                               nullptr, ffnp, FF, MM, FF, CC);
        gemm_tc<64,false,true><<<g_cc, 256>>>(ffnp, FF, W2 + (long)l*CC*FF, b2 + l*CC,
                                              xp, xp, CC, MM, CC, FF);
    }

    ln_kernel<<<MM, CC>>>(xp, lnfw, lnfb, xnp);

    dim3 g_head(VOC/64, MB128);
    gemm_tc<128,false,false><<<g_head, 256>>>(xnp, CC, headW, nullptr, nullptr,
                                              (float*)d_out, VOC, MM, VOC, CC);
}

// round 13
// speedup vs baseline: 1.0296x; 1.0272x over previous
#include <cuda_runtime.h>
#include <math.h>

// ---------------- problem constants ----------------
#define BB   4
#define TT   827
#define CC   256
#define HH   8
#define DHH  32
#define LL   12
#define FF   1024            // 4*C
#define MM   (BB*TT)         // 3308 rows
#define VOC  16384
#define QKVN 768

// ---------------- scratch (device globals; no allocs allowed) ----------------
__device__ float g_x   [MM*CC];
__device__ float g_xn  [MM*CC];
__device__ float g_qkv [MM*QKVN];
__device__ float g_y   [MM*CC];
__device__ float g_ffn [MM*FF];
__device__ float g_h   [(long)BB*TT*TT];
__device__ float g_z1  [3*BB*60];
__device__ float g_wqkv[(long)LL*QKVN*CC]; // packed + tf32-rounded
__device__ float g_bqkv[LL*QKVN];
__device__ float g_wor [(long)LL*CC*CC];   // tf32-rounded Wo
__device__ float g_w1r [(long)LL*FF*CC];   // tf32-rounded W1
__device__ float g_w2r [(long)LL*CC*FF];   // tf32-rounded W2
__device__ float g_hdr [(long)VOC*CC];     // tf32-rounded head_W

__device__ __forceinline__ float gelu_exact(float z) {
    return 0.5f * z * (1.0f + erff(z * 0.70710678118654752f));
}

__device__ __forceinline__ unsigned f2tf32(float x) {
    unsigned r;
    asm("cvt.rna.tf32.f32 %0, %1;" : "=r"(r) : "f"(x));
    return r;
}
__device__ __forceinline__ float tf32r(float x) {   // round-to-tf32, returned as float bits
    return __uint_as_float(f2tf32(x));
}

__device__ __forceinline__ void mma_tf32(float c[4], const unsigned a[4],
                                         unsigned b0, unsigned b1) {
    asm volatile(
        "mma.sync.aligned.m16n8k8.row.col.f32.tf32.tf32.f32 "
        "{%0,%1,%2,%3},{%4,%5,%6,%7},{%8,%9},{%0,%1,%2,%3};"
        : "+f"(c[0]), "+f"(c[1]), "+f"(c[2]), "+f"(c[3])
        : "r"(a[0]), "r"(a[1]), "r"(a[2]), "r"(a[3]), "r"(b0), "r"(b1));
}

// ---------------- fused QKV weight+bias packing (weights tf32-rounded) ----------------
__global__ void pack_qkv_kernel(const float* __restrict__ Wq, const float* __restrict__ Wk,
                                const float* __restrict__ Wv, const float* __restrict__ bq,
                                const float* __restrict__ bk, const float* __restrict__ bv) {
    const long nw = (long)LL*QKVN*CC;
    long idx = (long)blockIdx.x * blockDim.x + threadIdx.x;
    if (idx < nw) {
        int k = (int)(idx % CC);
        int n = (int)((idx / CC) % QKVN);
        int l = (int)(idx / ((long)CC*QKVN));
        const float* src;
        if      (n < 256) src = &Wq[((long)l*256 + n      )*CC];
        else if (n < 512) src = &Wk[((long)l*256 + n - 256)*CC];
        else              src = &Wv[((long)l*256 + n - 512)*CC];
        g_wqkv[idx] = tf32r(src[k]);
    } else if (idx < nw + (long)LL*QKVN) {
        int r = (int)(idx - nw);
        int n = r % QKVN;
        int l = r / QKVN;
        float v;
        if      (n < 256) v = bq[l*256 + n];
        else if (n < 512) v = bk[l*256 + n - 256];
        else              v = bv[l*256 + n - 512];
        g_bqkv[r] = v;
    }
}

// ---------------- round remaining weights to tf32 ----------------
__global__ void round_w_kernel(const float* __restrict__ Wo, const float* __restrict__ W1,
                               const float* __restrict__ W2, const float* __restrict__ headW) {
    const long nWo = (long)LL*CC*CC;
    const long nW1 = (long)LL*FF*CC;
    const long nW2 = (long)LL*CC*FF;
    const long nH  = (long)VOC*CC;
    long idx = (long)blockIdx.x * blockDim.x + threadIdx.x;
    if (idx < nWo)                        g_wor[idx]                 = tf32r(Wo[idx]);
    else if (idx < nWo + nW1)             g_w1r[idx - nWo]           = tf32r(W1[idx - nWo]);
    else if (idx < nWo + nW1 + nW2)       g_w2r[idx - nWo - nW1]     = tf32r(W2[idx - nWo - nW1]);
    else if (idx < nWo + nW1 + nW2 + nH)  g_hdr[idx - nWo - nW1 - nW2] = tf32r(headW[idx - nWo - nW1 - nW2]);
}

// ---------------- locality MLP ----------------
__global__ void loc1_kernel(const float* __restrict__ p1, const float* __restrict__ p2,
                            const float* __restrict__ p3, const float* __restrict__ W1,
                            const float* __restrict__ b1) {
    int mat = blockIdx.x / BB;
    int b   = blockIdx.x % BB;
    int j   = threadIdx.x;
    if (j >= 60) return;
    const float* p = (mat == 0) ? p1 : (mat == 1) ? p2 : p3;
    float s = b1[j];
    #pragma unroll
    for (int i = 0; i < 30; i++) s += p[b*30 + i] * W1[j*30 + i];
    g_z1[(mat*BB + b)*60 + j] = gelu_exact(s);
}

__global__ void zero_h_kernel() {
    long i = (long)blockIdx.x * blockDim.x + threadIdx.x;
    if (i < (long)BB*TT*TT) g_h[i] = 0.0f;
}

__global__ void loc2_kernel(const float* __restrict__ W2, const float* __restrict__ b2) {
    int idx = blockIdx.x * blockDim.x + threadIdx.x;
    const int total = 3 * BB * 65536;
    if (idx >= total) return;
    int mat = idx / (BB * 65536);
    int rem = idx % (BB * 65536);
    int b   = rem / 65536;
    int o   = rem % 65536;
    const float* z1 = &g_z1[(mat*BB + b)*60];
    const float* wr = &W2[(long)o * 60];
    float s = b2[o];
    #pragma unroll
    for (int j = 0; j < 60; j++) s += z1[j] * wr[j];
    int r = o >> 8, c = o & 255;
    int r0 = (mat == 0) ? 285 : 571;
    int c0 = (mat == 2) ? 286 : 0;
    g_h[((long)b*TT + (r0 + r))*TT + (c0 + c)] = s;
}

// ---------------- embedding ----------------
__global__ void embed_kernel(const float* __restrict__ dc, const float* __restrict__ z,
                             const float* __restrict__ frame, const float* __restrict__ cam,
                             const float* __restrict__ timee) {
    int idx = blockIdx.x * blockDim.x + threadIdx.x;
    if (idx >= MM*CC) return;
    int c = idx % CC;
    int t = (idx / CC) % TT;
    int b = idx / (CC * TT);
    float tok = (t < 572) ? dc[((long)b*572 + t)*CC + c]
                          : z [((long)b*256 + (t - 572))*CC + c];
    float role;
    if      (t < 256) role = frame[(t      )*CC + c];
    else if (t < 286) role = cam  [(t - 256)*CC + c];
    else if (t < 542) role = frame[(t - 286)*CC + c];
    else if (t < 572) role = cam  [(t - 542)*CC + c];
    else              role = frame[(t - 572)*CC + c];
    g_x[idx] = tok + role + timee[t*CC + c];
}

// ---------------- layernorm: single-pass; output tf32-rounded ----------------
__global__ void __launch_bounds__(CC) ln_kernel(const float* __restrict__ x,
                                                const float* __restrict__ w,
                                                const float* __restrict__ b,
                                                float* __restrict__ out) {
    int row = blockIdx.x;
    int tid = threadIdx.x;
    __shared__ float ws1[8], ws2[8];
    __shared__ float mv[2];
    float v = x[(long)row*CC + tid];

    float s1 = v, s2 = v * v;
    #pragma unroll
    for (int o = 16; o; o >>= 1) {
        s1 += __shfl_xor_sync(0xffffffffu, s1, o);
        s2 += __shfl_xor_sync(0xffffffffu, s2, o);
    }
    if ((tid & 31) == 0) { ws1[tid >> 5] = s1; ws2[tid >> 5] = s2; }
    __syncthreads();
    if (tid < 32) {
        float t1 = (tid < 8) ? ws1[tid] : 0.0f;
        float t2 = (tid < 8) ? ws2[tid] : 0.0f;
        #pragma unroll
        for (int o = 4; o; o >>= 1) {
            t1 += __shfl_xor_sync(0xffffffffu, t1, o);
            t2 += __shfl_xor_sync(0xffffffffu, t2, o);
        }
        if (tid == 0) {
            float mean = t1 * (1.0f / CC);
            float var  = t2 * (1.0f / CC) - mean * mean;
            mv[0] = mean;
            mv[1] = rsqrtf(var + 1e-5f);
        }
    }
    __syncthreads();
    out[(long)row*CC + tid] = tf32r((v - mv[0]) * mv[1] * w[tid] + b[tid]);
}

// ---------------- TF32 GEMM: 3-stage, single sync, NO cvt in hot loop ----------------
// Operands are pre-rounded to tf32 at production; fragments load raw bits.
#define SM_STRIDE 20
#define NSTAGE 3

__device__ __forceinline__ void cp_async16(unsigned dst, const void* src, int bytes) {
    asm volatile("cp.async.ca.shared.global [%0], [%1], 16, %2;\n"
                 :: "r"(dst), "l"(src), "r"(bytes));
}

template<int BM, bool DO_GELU, bool DO_RES, bool ROUND_OUT>
__global__ void __launch_bounds__(256)
gemm_tc(const float* __restrict__ A, int lda,
        const float* __restrict__ W,
        const float* __restrict__ bias,
        const float* __restrict__ res,
        float* __restrict__ out, int ldo,
        int M, int N, int K) {
    constexpr int MI = BM / 64;
    __shared__ __align__(16) float As[NSTAGE][BM*SM_STRIDE];
    __shared__ __align__(16) float Bs[NSTAGE][64*SM_STRIDE];

    const int tid  = threadIdx.x;
    const int m0   = blockIdx.y * BM;
    const int n0   = blockIdx.x * 64;
    const int warp = tid >> 5, lane = tid & 31;
    const int wm = warp >> 1, wn = warp & 1;
    const int grp = lane >> 2, qd = lane & 3;

    float c[MI][4][4];
    #pragma unroll
    for (int i = 0; i < MI; i++)
        #pragma unroll
        for (int j = 0; j < 4; j++)
            #pragma unroll
            for (int k = 0; k < 4; k++) c[i][j][k] = 0.0f;

    const int a_r0 = tid >> 2,         a_c0 = (tid & 3) << 2;
    const int a_r1 = (tid + 256) >> 2, a_c1 = (tid & 3) << 2;
    const int b_r  = tid >> 2,         b_c  = (tid & 3) << 2;

    unsigned sA[NSTAGE], sB[NSTAGE];
    #pragma unroll
    for (int i = 0; i < NSTAGE; i++) {
        sA[i] = (unsigned)__cvta_generic_to_shared(&As[i][0]);
        sB[i] = (unsigned)__cvta_generic_to_shared(&Bs[i][0]);
    }

    auto load_tiles = [&](int k0, int buf) {
        int m = m0 + a_r0;
        const float* src = A + (long)(m < M ? m : 0) * lda + k0 + a_c0;
        cp_async16(sA[buf] + (a_r0*SM_STRIDE + a_c0)*4, src, m < M ? 16 : 0);
        if (MI == 2) {
            m = m0 + a_r1;
            src = A + (long)(m < M ? m : 0) * lda + k0 + a_c1;
            cp_async16(sA[buf] + (a_r1*SM_STRIDE + a_c1)*4, src, m < M ? 16 : 0);
        }
        const float* srcb = W + (long)(n0 + b_r) * K + k0 + b_c;
        cp_async16(sB[buf] + (b_r*SM_STRIDE + b_c)*4, srcb, 16);
        asm volatile("cp.async.commit_group;\n");
    };

    auto compute = [&](int buf) {
        const unsigned* pa = reinterpret_cast<const unsigned*>(As[buf]);
        const unsigned* pb = reinterpret_cast<const unsigned*>(Bs[buf]);
        #pragma unroll
        for (int ks = 0; ks < 2; ks++) {
            const int kk = ks * 8;
            unsigned a[MI][4], b[4][2];
            #pragma unroll
            for (int mi = 0; mi < MI; mi++) {
                int r = wm*(16*MI) + mi*16 + grp;
                a[mi][0] = pa[(r    )*SM_STRIDE + kk + qd    ];
                a[mi][1] = pa[(r + 8)*SM_STRIDE + kk + qd    ];
                a[mi][2] = pa[(r    )*SM_STRIDE + kk + qd + 4];
                a[mi][3] = pa[(r + 8)*SM_STRIDE + kk + qd + 4];
            }
            #pragma unroll
            for (int ni = 0; ni < 4; ni++) {
                int n = wn*32 + ni*8 + grp;
                b[ni][0] = pb[n*SM_STRIDE + kk + qd    ];
                b[ni][1] = pb[n*SM_STRIDE + kk + qd + 4];
            }
            #pragma unroll
            for (int mi = 0; mi < MI; mi++)
                #pragma unroll
                for (int ni = 0; ni < 4; ni++)
                    mma_tf32(c[mi][ni], a[mi], b[ni][0], b[ni][1]);
        }
    };

    const int nt = K >> 4;
    load_tiles(0, 0);
    load_tiles(16, 1);
    for (int t = 0; t < nt; t++) {
        if (t + 1 < nt) { asm volatile("cp.async.wait_group 1;\n"); }
        else            { asm volatile("cp.async.wait_group 0;\n"); }
        __syncthreads();
        if (t + 2 < nt) load_tiles((t + 2) << 4, (t + 2) % NSTAGE);
        compute(t % NSTAGE);
    }

    #pragma unroll
    for (int mi = 0; mi < MI; mi++) {
        #pragma unroll
        for (int ni = 0; ni < 4; ni++) {
            int col = n0 + wn*32 + ni*8 + 2*qd;
            float bsum0 = bias ? bias[col]     : 0.0f;
            float bsum1 = bias ? bias[col + 1] : 0.0f;
            #pragma unroll
            for (int rr = 0; rr < 2; rr++) {
                int row = m0 + wm*(16*MI) + mi*16 + grp + rr*8;
                if (row >= M) continue;
                float v0 = c[mi][ni][rr*2 + 0] + bsum0;
                float v1 = c[mi][ni][rr*2 + 1] + bsum1;
                if (DO_GELU) { v0 = gelu_exact(v0); v1 = gelu_exact(v1); }
                if (DO_RES) {
                    const float2 rv = *reinterpret_cast<const float2*>(&res[(long)row*ldo + col]);
                    v0 += rv.x; v1 += rv.y;
                }
                if (ROUND_OUT) { v0 = tf32r(v0); v1 = tf32r(v1); }
                float2 ov; ov.x = v0; ov.y = v1;
                *reinterpret_cast<float2*>(&out[(long)row*ldo + col]) = ov;
            }
        }
    }
}

// ---------------- tensor-core flash attention (R8-proven; output tf32-rounded) ----------------
#define ATQ 64
#define ATK 64
#define QKS 36
#define PSS 68

__global__ void __launch_bounds__(256) attn_kernel(int adaptive) {
    __shared__ __align__(16) float Qs[ATQ*QKS];
    __shared__ __align__(16) float Ks[ATK*QKS];
    __shared__ __align__(16) float Vs[ATK*QKS];
    __shared__ __align__(16) float Ps[ATQ*PSS];
    __shared__ float m_s[ATQ], l_s[ATQ], corr_s[ATQ];

    const int tile = blockIdx.x;
    const int bh   = blockIdx.y;
    const int b = bh >> 3, h = bh & 7;
    const int t = threadIdx.x;
    const int q0 = tile * ATQ;
    const int warp = t >> 5, lane = t & 31;
    const int wm = warp >> 1, wn = warp & 1;
    const int grp = lane >> 2, qd = lane & 3;
    const int rv = t >> 2, sub = t & 3;
    const float scale = 0.1767766952966369f;

    {
        int r = q0 + rv;
        float4 a0 = {0,0,0,0}, a1 = {0,0,0,0};
        if (r < TT) {
            const float4* src = reinterpret_cast<const float4*>(
                &g_qkv[((long)(b*TT + r))*QKVN + h*DHH + sub*8]);
            a0 = src[0]; a1 = src[1];
        }
        float4* qdst = reinterpret_cast<float4*>(&Qs[rv*QKS + sub*8]);
        qdst[0] = a0; qdst[1] = a1;
    }
    if (t < ATQ) { m_s[t] = -1e30f; l_s[t] = 0.0f; }
    __syncthreads();

    unsigned aq[4][4];
    {
        int r0 = wm*16 + grp;
        #pragma unroll
        for (int ks = 0; ks < 4; ks++) {
            int kk = ks*8;
            aq[ks][0] = f2tf32(Qs[(r0    )*QKS + kk + qd    ]);
            aq[ks][1] = f2tf32(Qs[(r0 + 8)*QKS + kk + qd    ]);
            aq[ks][2] = f2tf32(Qs[(r0    )*QKS + kk + qd + 4]);
            aq[ks][3] = f2tf32(Qs[(r0 + 8)*QKS + kk + qd + 4]);
        }
    }

    float co[2][4] = {{0,0,0,0},{0,0,0,0}};

    for (int kt = 0; kt <= tile; kt++) {
        const int k0 = kt * ATK;
        __syncthreads();

        {
            int r = k0 + rv;
            float4 kv0 = {0,0,0,0}, kv1 = {0,0,0,0}, vv0 = {0,0,0,0}, vv1 = {0,0,0,0};
            if (r < TT) {
                const float4* ks = reinterpret_cast<const float4*>(
                    &g_qkv[((long)(b*TT + r))*QKVN + 256 + h*DHH + sub*8]);
                kv0 = ks[0]; kv1 = ks[1];
                const float4* vs = reinterpret_cast<const float4*>(
                    &g_qkv[((long)(b*TT + r))*QKVN + 512 + h*DHH + sub*8]);
                vv0 = vs[0]; vv1 = vs[1];
            }
            float4* kd = reinterpret_cast<float4*>(&Ks[rv*QKS + sub*8]);
            kd[0] = kv0; kd[1] = kv1;
            float4* vd = reinterpret_cast<float4*>(&Vs[rv*QKS + sub*8]);
            vd[0] = vv0; vd[1] = vv1;
        }
        __syncthreads();

        float cs[4][4];
        #pragma unroll
        for (int ni = 0; ni < 4; ni++)
            #pragma unroll
            for (int j = 0; j < 4; j++) cs[ni][j] = 0.0f;
        #pragma unroll
        for (int ks = 0; ks < 4; ks++) {
            int kk = ks*8;
            unsigned bf[4][2];
            #pragma unroll
            for (int ni = 0; ni < 4; ni++) {
                int kn = wn*32 + ni*8 + grp;
                bf[ni][0] = f2tf32(Ks[kn*QKS + kk + qd    ]);
                bf[ni][1] = f2tf32(Ks[kn*QKS + kk + qd + 4]);
            }
            #pragma unroll
            for (int ni = 0; ni < 4; ni++)
                mma_tf32(cs[ni], aq[ks], bf[ni][0], bf[ni][1]);
        }

        const int r0 = wm*16 + grp;
        #pragma unroll
        for (int rr = 0; rr < 2; rr++) {
            int rl = r0 + rr*8;
            int q  = q0 + rl;
            bool qvalid = (q < TT);
            #pragma unroll
            for (int ni = 0; ni < 4; ni++) {
                int cl = wn*32 + ni*8 + 2*qd;
                int kc = k0 + cl;
                float v0, v1;
                if (kc > q || !qvalid) v0 = -1e30f;
                else {
                    float bias = adaptive ? g_h[((long)b*TT + q)*TT + kc] : 0.0f;
                    v0 = cs[ni][rr*2 + 0]*scale + bias;
                }
                if (kc + 1 > q || !qvalid) v1 = -1e30f;
                else {
                    float bias = adaptive ? g_h[((long)b*TT + q)*TT + kc + 1] : 0.0f;
                    v1 = cs[ni][rr*2 + 1]*scale + bias;
                }
                float2 sv; sv.x = v0; sv.y = v1;
                *reinterpret_cast<float2*>(&Ps[rl*PSS + cl]) = sv;
            }
        }
        __syncthreads();

        {
            float* pr = &Ps[rv*PSS + sub*16];
            float tmax = -1e30f;
            #pragma unroll
            for (int j = 0; j < 16; j++) tmax = fmaxf(tmax, pr[j]);
            tmax = fmaxf(tmax, __shfl_xor_sync(0xffffffffu, tmax, 1));
            tmax = fmaxf(tmax, __shfl_xor_sync(0xffffffffu, tmax, 2));
            float m_old = m_s[rv];
            float m_new = fmaxf(m_old, tmax);
            float tsum = 0.0f;
            #pragma unroll
            for (int j = 0; j < 16; j++) {
                float p = __expf(pr[j] - m_new);
                pr[j] = p;
                tsum += p;
            }
            tsum += __shfl_xor_sync(0xffffffffu, tsum, 1);
            tsum += __shfl_xor_sync(0xffffffffu, tsum, 2);
            if (sub == 0) {
                float corr = __expf(m_old - m_new);
                corr_s[rv] = corr;
                l_s[rv]    = l_s[rv]*corr + tsum;
                m_s[rv]    = m_new;
            }
        }
        __syncthreads();

        {
            float c0f = corr_s[r0];
            float c1f = corr_s[r0 + 8];
            #pragma unroll
            for (int nj = 0; nj < 2; nj++) {
                co[nj][0] *= c0f; co[nj][1] *= c0f;
                co[nj][2] *= c1f; co[nj][3] *= c1f;
            }
            #pragma unroll
            for (int ks = 0; ks < 8; ks++) {
                int kk = ks*8;
                unsigned ap[4];
                ap[0] = f2tf32(Ps[(r0    )*PSS + kk + qd    ]);
                ap[1] = f2tf32(Ps[(r0 + 8)*PSS + kk + qd    ]);
                ap[2] = f2tf32(Ps[(r0    )*PSS + kk + qd + 4]);
                ap[3] = f2tf32(Ps[(r0 + 8)*PSS + kk + qd + 4]);
                #pragma unroll
                for (int nj = 0; nj < 2; nj++) {
                    int nc = wn*16 + nj*8 + grp;
                    unsigned b0 = f2tf32(Vs[(kk + qd    )*QKS + nc]);
                    unsigned b1 = f2tf32(Vs[(kk + qd + 4)*QKS + nc]);
                    mma_tf32(co[nj], ap, b0, b1);
                }
            }
        }
    }

    {
        const int r0 = wm*16 + grp;
        int qa = q0 + r0, qb = q0 + r0 + 8;
        float inva = (qa < TT) ? 1.0f / l_s[r0]     : 0.0f;
        float invb = (qb < TT) ? 1.0f / l_s[r0 + 8] : 0.0f;
        #pragma unroll
        for (int nj = 0; nj < 2; nj++) {
            int col = wn*16 + nj*8 + 2*qd;
            if (qa < TT) {
                float2 ov; ov.x = tf32r(co[nj][0]*inva); ov.y = tf32r(co[nj][1]*inva);
                *reinterpret_cast<float2*>(&g_y[((long)(b*TT + qa))*CC + h*DHH + col]) = ov;
            }
            if (qb < TT) {
                float2 ov; ov.x = tf32r(co[nj][2]*invb); ov.y = tf32r(co[nj][3]*invb);
                *reinterpret_cast<float2*>(&g_y[((long)(b*TT + qb))*CC + h*DHH + col]) = ov;
            }
        }
    }
}

// ---------------- launch ----------------
extern "C" void kernel_launch(void* const* d_in, const int* in_sizes, int n_in,
                              void* d_out, int out_size) {
    const float* dc      = (const float*)d_in[0];
    const float* z       = (const float*)d_in[1];
    const float* p1      = (const float*)d_in[2];
    const float* p2      = (const float*)d_in[3];
    const float* p3      = (const float*)d_in[4];
    const float* frame   = (const float*)d_in[5];
    const float* cam     = (const float*)d_in[6];
    const float* timee   = (const float*)d_in[7];
    const float* locW1   = (const float*)d_in[8];
    const float* locb1   = (const float*)d_in[9];
    const float* locW2   = (const float*)d_in[10];
    const float* locb2   = (const float*)d_in[11];
    const float* ln1w    = (const float*)d_in[12];
    const float* ln1b    = (const float*)d_in[13];
    const float* Wq      = (const float*)d_in[14];
    const float* bq      = (const float*)d_in[15];
    const float* Wk      = (const float*)d_in[16];
    const float* bk      = (const float*)d_in[17];
    const float* Wv      = (const float*)d_in[18];
    const float* bv      = (const float*)d_in[19];
    const float* Wo      = (const float*)d_in[20];
    const float* bo      = (const float*)d_in[21];
    const float* ln2w    = (const float*)d_in[22];
    const float* ln2b    = (const float*)d_in[23];
    const float* W1      = (const float*)d_in[24];
    const float* b1      = (const float*)d_in[25];
    const float* W2      = (const float*)d_in[26];
    const float* b2      = (const float*)d_in[27];
    const float* lnfw    = (const float*)d_in[28];
    const float* lnfb    = (const float*)d_in[29];
    const float* headW   = (const float*)d_in[30];

    float *xp, *xnp, *qkvp, *yp, *ffnp, *wqkvp, *bqkvp, *worp, *w1rp, *w2rp, *hdrp;
    cudaGetSymbolAddress((void**)&xp,    g_x);
    cudaGetSymbolAddress((void**)&xnp,   g_xn);
    cudaGetSymbolAddress((void**)&qkvp,  g_qkv);
    cudaGetSymbolAddress((void**)&yp,    g_y);
    cudaGetSymbolAddress((void**)&ffnp,  g_ffn);
    cudaGetSymbolAddress((void**)&wqkvp, g_wqkv);
    cudaGetSymbolAddress((void**)&bqkvp, g_bqkv);
    cudaGetSymbolAddress((void**)&worp,  g_wor);
    cudaGetSymbolAddress((void**)&w1rp,  g_w1r);
    cudaGetSymbolAddress((void**)&w2rp,  g_w2r);
    cudaGetSymbolAddress((void**)&hdrp,  g_hdr);

    const int MB128 = (MM + 127) / 128;  // 26
    dim3 g_qkvg(QKVN/64, MB128);
    dim3 g_cc(CC/64, MB128);
    dim3 g_ff(FF/64, MB128);
    dim3 attn_grid((TT + ATQ - 1)/ATQ, BB*HH);

    {
        long np = (long)LL*QKVN*CC + (long)LL*QKVN;
        pack_qkv_kernel<<<(int)((np + 255) / 256), 256>>>(Wq, Wk, Wv, bq, bk, bv);
        long nr = (long)LL*CC*CC + (long)LL*FF*CC + (long)LL*CC*FF + (long)VOC*CC;
        round_w_kernel<<<(int)((nr + 255) / 256), 256>>>(Wo, W1, W2, headW);
    }
    embed_kernel<<<(MM*CC + 255) / 256, 256>>>(dc, z, frame, cam, timee);

    for (int l = 0; l < LL; l++) {
        ln_kernel<<<MM, CC>>>(xp, ln1w + l*CC, ln1b + l*CC, xnp);

        gemm_tc<128,false,false,true><<<g_qkvg, 256>>>(xnp, CC, wqkvp + (long)l*QKVN*CC,
                                                       bqkvp + l*QKVN, nullptr, qkvp, QKVN,
                                                       MM, QKVN, CC);

        if (l == 0) {
            long nh = (long)BB*TT*TT;
            zero_h_kernel<<<(int)((nh + 255) / 256), 256>>>();
            loc1_kernel<<<3*BB, 64>>>(p1, p2, p3, locW1, locb1);
            loc2_kernel<<<(3*BB*65536 + 127) / 128, 128>>>(locW2, locb2);
        }

        attn_kernel<<<attn_grid, 256>>>((l % 2 == 0) ? 1 : 0);

        gemm_tc<128,false,true,false><<<g_cc, 256>>>(yp, CC, worp + (long)l*CC*CC, bo + l*CC,
                                                     xp, xp, CC, MM, CC, CC);

        ln_kernel<<<MM, CC>>>(xp, ln2w + l*CC, ln2b + l*CC, xnp);

        gemm_tc<128,true,false,true><<<g_ff, 256>>>(xnp, CC, w1rp + (long)l*FF*CC, b1 + (long)l*FF,
                                                    nullptr, ffnp, FF, MM, FF, CC);
        gemm_tc<128,false,true,false><<<g_cc, 256>>>(ffnp, FF, w2rp + (long)l*CC*FF, b2 + l*CC,
                                                     xp, xp, CC, MM, CC, FF);
    }

    ln_kernel<<<MM, CC>>>(xp, lnfw, lnfb, xnp);

    dim3 g_head(VOC/64, MB128);
    gemm_tc<128,false,false,false><<<g_head, 256>>>(xnp, CC, hdrp, nullptr, nullptr,
                                                    (float*)d_out, VOC, MM, VOC, CC);
}

// round 16
// speedup vs baseline: 1.0659x; 1.0352x over previous
#include <cuda_runtime.h>
#include <math.h>

// ---------------- problem constants ----------------
#define BB   4
#define TT   827
#define CC   256
#define HH   8
#define DHH  32
#define LL   12
#define FF   1024            // 4*C
#define MM   (BB*TT)         // 3308 rows
#define VOC  16384
#define QKVN 768

// ---------------- scratch (device globals; no allocs allowed) ----------------
__device__ float g_x   [MM*CC];
__device__ float g_xn  [MM*CC];
__device__ float g_qkv [MM*QKVN];
__device__ float g_y   [MM*CC];
__device__ float g_ffn [MM*FF];
__device__ float g_h   [(long)BB*TT*TT];
__device__ float g_z1  [3*BB*60];
__device__ float g_wqkv[(long)LL*QKVN*CC]; // packed + tf32-rounded
__device__ float g_bqkv[LL*QKVN];
__device__ float g_wor [(long)LL*CC*CC];   // tf32-rounded Wo
__device__ float g_w1r [(long)LL*FF*CC];   // tf32-rounded W1
__device__ float g_w2r [(long)LL*CC*FF];   // tf32-rounded W2
__device__ float g_hdr [(long)VOC*CC];     // tf32-rounded head_W

__device__ __forceinline__ float gelu_exact(float z) {
    return 0.5f * z * (1.0f + erff(z * 0.70710678118654752f));
}

__device__ __forceinline__ unsigned f2tf32(float x) {
    unsigned r;
    asm("cvt.rna.tf32.f32 %0, %1;" : "=r"(r) : "f"(x));
    return r;
}
__device__ __forceinline__ float tf32r(float x) {   // round-to-tf32, returned as float bits
    return __uint_as_float(f2tf32(x));
}

__device__ __forceinline__ void mma_tf32(float c[4], const unsigned a[4],
                                         unsigned b0, unsigned b1) {
    asm volatile(
        "mma.sync.aligned.m16n8k8.row.col.f32.tf32.tf32.f32 "
        "{%0,%1,%2,%3},{%4,%5,%6,%7},{%8,%9},{%0,%1,%2,%3};"
        : "+f"(c[0]), "+f"(c[1]), "+f"(c[2]), "+f"(c[3])
        : "r"(a[0]), "r"(a[1]), "r"(a[2]), "r"(a[3]), "r"(b0), "r"(b1));
}

// ---------------- fused QKV weight+bias packing (weights tf32-rounded) ----------------
__global__ void pack_qkv_kernel(const float* __restrict__ Wq, const float* __restrict__ Wk,
                                const float* __restrict__ Wv, const float* __restrict__ bq,
                                const float* __restrict__ bk, const float* __restrict__ bv) {
    const long nw = (long)LL*QKVN*CC;
    long idx = (long)blockIdx.x * blockDim.x + threadIdx.x;
    if (idx < nw) {
        int k = (int)(idx % CC);
        int n = (int)((idx / CC) % QKVN);
        int l = (int)(idx / ((long)CC*QKVN));
        const float* src;
        if      (n < 256) src = &Wq[((long)l*256 + n      )*CC];
        else if (n < 512) src = &Wk[((long)l*256 + n - 256)*CC];
        else              src = &Wv[((long)l*256 + n - 512)*CC];
        g_wqkv[idx] = tf32r(src[k]);
    } else if (idx < nw + (long)LL*QKVN) {
        int r = (int)(idx - nw);
        int n = r % QKVN;
        int l = r / QKVN;
        float v;
        if      (n < 256) v = bq[l*256 + n];
        else if (n < 512) v = bk[l*256 + n - 256];
        else              v = bv[l*256 + n - 512];
        g_bqkv[r] = v;
    }
}

// ---------------- round remaining weights to tf32 ----------------
__global__ void round_w_kernel(const float* __restrict__ Wo, const float* __restrict__ W1,
                               const float* __restrict__ W2, const float* __restrict__ headW) {
    const long nWo = (long)LL*CC*CC;
    const long nW1 = (long)LL*FF*CC;
    const long nW2 = (long)LL*CC*FF;
    const long nH  = (long)VOC*CC;
    long idx = (long)blockIdx.x * blockDim.x + threadIdx.x;
    if (idx < nWo)                        g_wor[idx]                 = tf32r(Wo[idx]);
    else if (idx < nWo + nW1)             g_w1r[idx - nWo]           = tf32r(W1[idx - nWo]);
    else if (idx < nWo + nW1 + nW2)       g_w2r[idx - nWo - nW1]     = tf32r(W2[idx - nWo - nW1]);
    else if (idx < nWo + nW1 + nW2 + nH)  g_hdr[idx - nWo - nW1 - nW2] = tf32r(headW[idx - nWo - nW1 - nW2]);
}

// ---------------- locality MLP ----------------
__global__ void loc1_kernel(const float* __restrict__ p1, const float* __restrict__ p2,
                            const float* __restrict__ p3, const float* __restrict__ W1,
                            const float* __restrict__ b1) {
    int mat = blockIdx.x / BB;
    int b   = blockIdx.x % BB;
    int j   = threadIdx.x;
    if (j >= 60) return;
    const float* p = (mat == 0) ? p1 : (mat == 1) ? p2 : p3;
    float s = b1[j];
    #pragma unroll
    for (int i = 0; i < 30; i++) s += p[b*30 + i] * W1[j*30 + i];
    g_z1[(mat*BB + b)*60 + j] = gelu_exact(s);
}

__global__ void zero_h_kernel() {
    long i = (long)blockIdx.x * blockDim.x + threadIdx.x;
    if (i < (long)BB*TT*TT) g_h[i] = 0.0f;
}

__global__ void loc2_kernel(const float* __restrict__ W2, const float* __restrict__ b2) {
    int idx = blockIdx.x * blockDim.x + threadIdx.x;
    const int total = 3 * BB * 65536;
    if (idx >= total) return;
    int mat = idx / (BB * 65536);
    int rem = idx % (BB * 65536);
    int b   = rem / 65536;
    int o   = rem % 65536;
    const float* z1 = &g_z1[(mat*BB + b)*60];
    const float* wr = &W2[(long)o * 60];
    float s = b2[o];
    #pragma unroll
    for (int j = 0; j < 60; j++) s += z1[j] * wr[j];
    int r = o >> 8, c = o & 255;
    int r0 = (mat == 0) ? 285 : 571;
    int c0 = (mat == 2) ? 286 : 0;
    g_h[((long)b*TT + (r0 + r))*TT + (c0 + c)] = s;
}

// ---------------- embedding ----------------
__global__ void embed_kernel(const float* __restrict__ dc, const float* __restrict__ z,
                             const float* __restrict__ frame, const float* __restrict__ cam,
                             const float* __restrict__ timee) {
    int idx = blockIdx.x * blockDim.x + threadIdx.x;
    if (idx >= MM*CC) return;
    int c = idx % CC;
    int t = (idx / CC) % TT;
    int b = idx / (CC * TT);
    float tok = (t < 572) ? dc[((long)b*572 + t)*CC + c]
                          : z [((long)b*256 + (t - 572))*CC + c];
    float role;
    if      (t < 256) role = frame[(t      )*CC + c];
    else if (t < 286) role = cam  [(t - 256)*CC + c];
    else if (t < 542) role = frame[(t - 286)*CC + c];
    else if (t < 572) role = cam  [(t - 542)*CC + c];
    else              role = frame[(t - 572)*CC + c];
    g_x[idx] = tok + role + timee[t*CC + c];
}

// ---------------- layernorm: single-pass; output tf32-rounded ----------------
__global__ void __launch_bounds__(CC) ln_kernel(const float* __restrict__ x,
                                                const float* __restrict__ w,
                                                const float* __restrict__ b,
                                                float* __restrict__ out) {
    int row = blockIdx.x;
    int tid = threadIdx.x;
    __shared__ float ws1[8], ws2[8];
    __shared__ float mv[2];
    float v = x[(long)row*CC + tid];

    float s1 = v, s2 = v * v;
    #pragma unroll
    for (int o = 16; o; o >>= 1) {
        s1 += __shfl_xor_sync(0xffffffffu, s1, o);
        s2 += __shfl_xor_sync(0xffffffffu, s2, o);
    }
    if ((tid & 31) == 0) { ws1[tid >> 5] = s1; ws2[tid >> 5] = s2; }
    __syncthreads();
    if (tid < 32) {
        float t1 = (tid < 8) ? ws1[tid] : 0.0f;
        float t2 = (tid < 8) ? ws2[tid] : 0.0f;
        #pragma unroll
        for (int o = 4; o; o >>= 1) {
            t1 += __shfl_xor_sync(0xffffffffu, t1, o);
            t2 += __shfl_xor_sync(0xffffffffu, t2, o);
        }
        if (tid == 0) {
            float mean = t1 * (1.0f / CC);
            float var  = t2 * (1.0f / CC) - mean * mean;
            mv[0] = mean;
            mv[1] = rsqrtf(var + 1e-5f);
        }
    }
    __syncthreads();
    out[(long)row*CC + tid] = tf32r((v - mv[0]) * mv[1] * w[tid] + b[tid]);
}

// ---------------- TF32 GEMM: proven 2-stage pipeline, NO cvt in hot loop ----------------
// Operands are pre-rounded to tf32 at production; fragments load raw bits.
#define SM_STRIDE 20

__device__ __forceinline__ void cp_async16(unsigned dst, const void* src, int bytes) {
    asm volatile("cp.async.ca.shared.global [%0], [%1], 16, %2;\n"
                 :: "r"(dst), "l"(src), "r"(bytes));
}

template<int BM, bool DO_GELU, bool DO_RES, bool ROUND_OUT>
__global__ void __launch_bounds__(256)
gemm_tc(const float* __restrict__ A, int lda,
        const float* __restrict__ W,
        const float* __restrict__ bias,
        const float* __restrict__ res,
        float* __restrict__ out, int ldo,
        int M, int N, int K) {
    constexpr int MI = BM / 64;
    __shared__ __align__(16) float As[2][BM*SM_STRIDE];
    __shared__ __align__(16) float Bs[2][64*SM_STRIDE];

    const int tid  = threadIdx.x;
    const int m0   = blockIdx.y * BM;
    const int n0   = blockIdx.x * 64;
    const int warp = tid >> 5, lane = tid & 31;
    const int wm = warp >> 1, wn = warp & 1;
    const int grp = lane >> 2, qd = lane & 3;

    float c[MI][4][4];
    #pragma unroll
    for (int i = 0; i < MI; i++)
        #pragma unroll
        for (int j = 0; j < 4; j++)
            #pragma unroll
            for (int k = 0; k < 4; k++) c[i][j][k] = 0.0f;

    const int a_r0 = tid >> 2,         a_c0 = (tid & 3) << 2;
    const int a_r1 = (tid + 256) >> 2, a_c1 = (tid & 3) << 2;
    const int b_r  = tid >> 2,         b_c  = (tid & 3) << 2;

    unsigned sA[2], sB[2];
    sA[0] = (unsigned)__cvta_generic_to_shared(&As[0][0]);
    sA[1] = (unsigned)__cvta_generic_to_shared(&As[1][0]);
    sB[0] = (unsigned)__cvta_generic_to_shared(&Bs[0][0]);
    sB[1] = (unsigned)__cvta_generic_to_shared(&Bs[1][0]);

    auto load_tiles = [&](int k0, int buf) {
        int m = m0 + a_r0;
        const float* src = A + (long)(m < M ? m : 0) * lda + k0 + a_c0;
        cp_async16(sA[buf] + (a_r0*SM_STRIDE + a_c0)*4, src, m < M ? 16 : 0);
        if (MI == 2) {
            m = m0 + a_r1;
            src = A + (long)(m < M ? m : 0) * lda + k0 + a_c1;
            cp_async16(sA[buf] + (a_r1*SM_STRIDE + a_c1)*4, src, m < M ? 16 : 0);
        }
        const float* srcb = W + (long)(n0 + b_r) * K + k0 + b_c;
        cp_async16(sB[buf] + (b_r*SM_STRIDE + b_c)*4, srcb, 16);
        asm volatile("cp.async.commit_group;\n");
    };

    auto compute = [&](int buf) {
        const unsigned* pa = reinterpret_cast<const unsigned*>(As[buf]);
        const unsigned* pb = reinterpret_cast<const unsigned*>(Bs[buf]);
        #pragma unroll
        for (int ks = 0; ks < 2; ks++) {
            const int kk = ks * 8;
            unsigned a[MI][4], b[4][2];
            #pragma unroll
            for (int mi = 0; mi < MI; mi++) {
                int r = wm*(16*MI) + mi*16 + grp;
                a[mi][0] = pa[(r    )*SM_STRIDE + kk + qd    ];
                a[mi][1] = pa[(r + 8)*SM_STRIDE + kk + qd    ];
                a[mi][2] = pa[(r    )*SM_STRIDE + kk + qd + 4];
                a[mi][3] = pa[(r + 8)*SM_STRIDE + kk + qd + 4];
            }
            #pragma unroll
            for (int ni = 0; ni < 4; ni++) {
                int n = wn*32 + ni*8 + grp;
                b[ni][0] = pb[n*SM_STRIDE + kk + qd    ];
                b[ni][1] = pb[n*SM_STRIDE + kk + qd + 4];
            }
            #pragma unroll
            for (int mi = 0; mi < MI; mi++)
                #pragma unroll
                for (int ni = 0; ni < 4; ni++)
                    mma_tf32(c[mi][ni], a[mi], b[ni][0], b[ni][1]);
        }
    };

    const int nt = K >> 4;
    load_tiles(0, 0);
    for (int t = 0; t < nt; t++) {
        const int buf = t & 1;
        if (t + 1 < nt) {
            load_tiles((t + 1) << 4, 1 - buf);
            asm volatile("cp.async.wait_group 1;\n");
        } else {
            asm volatile("cp.async.wait_group 0;\n");
        }
        __syncthreads();
        compute(buf);
        __syncthreads();
    }

    #pragma unroll
    for (int mi = 0; mi < MI; mi++) {
        #pragma unroll
        for (int ni = 0; ni < 4; ni++) {
            int col = n0 + wn*32 + ni*8 + 2*qd;
            float bsum0 = bias ? bias[col]     : 0.0f;
            float bsum1 = bias ? bias[col + 1] : 0.0f;
            #pragma unroll
            for (int rr = 0; rr < 2; rr++) {
                int row = m0 + wm*(16*MI) + mi*16 + grp + rr*8;
                if (row >= M) continue;
                float v0 = c[mi][ni][rr*2 + 0] + bsum0;
                float v1 = c[mi][ni][rr*2 + 1] + bsum1;
                if (DO_GELU) { v0 = gelu_exact(v0); v1 = gelu_exact(v1); }
                if (DO_RES) {
                    const float2 rv = *reinterpret_cast<const float2*>(&res[(long)row*ldo + col]);
                    v0 += rv.x; v1 += rv.y;
                }
                if (ROUND_OUT) { v0 = tf32r(v0); v1 = tf32r(v1); }
                float2 ov; ov.x = v0; ov.y = v1;
                *reinterpret_cast<float2*>(&out[(long)row*ldo + col]) = ov;
            }
        }
    }
}

// ---------------- tensor-core flash attention (R8-proven; output tf32-rounded) ----------------
#define ATQ 64
#define ATK 64
#define QKS 36
#define PSS 68

__global__ void __launch_bounds__(256) attn_kernel(int adaptive) {
    __shared__ __align__(16) float Qs[ATQ*QKS];
    __shared__ __align__(16) float Ks[ATK*QKS];
    __shared__ __align__(16) float Vs[ATK*QKS];
    __shared__ __align__(16) float Ps[ATQ*PSS];
    __shared__ float m_s[ATQ], l_s[ATQ], corr_s[ATQ];

    const int tile = blockIdx.x;
    const int bh   = blockIdx.y;
    const int b = bh >> 3, h = bh & 7;
    const int t = threadIdx.x;
    const int q0 = tile * ATQ;
    const int warp = t >> 5, lane = t & 31;
    const int wm = warp >> 1, wn = warp & 1;
    const int grp = lane >> 2, qd = lane & 3;
    const int rv = t >> 2, sub = t & 3;
    const float scale = 0.1767766952966369f;

    {
        int r = q0 + rv;
        float4 a0 = {0,0,0,0}, a1 = {0,0,0,0};
        if (r < TT) {
            const float4* src = reinterpret_cast<const float4*>(
                &g_qkv[((long)(b*TT + r))*QKVN + h*DHH + sub*8]);
            a0 = src[0]; a1 = src[1];
        }
        float4* qdst = reinterpret_cast<float4*>(&Qs[rv*QKS + sub*8]);
        qdst[0] = a0; qdst[1] = a1;
    }
    if (t < ATQ) { m_s[t] = -1e30f; l_s[t] = 0.0f; }
    __syncthreads();

    unsigned aq[4][4];
    {
        int r0 = wm*16 + grp;
        #pragma unroll
        for (int ks = 0; ks < 4; ks++) {
            int kk = ks*8;
            aq[ks][0] = f2tf32(Qs[(r0    )*QKS + kk + qd    ]);
            aq[ks][1] = f2tf32(Qs[(r0 + 8)*QKS + kk + qd    ]);
            aq[ks][2] = f2tf32(Qs[(r0    )*QKS + kk + qd + 4]);
            aq[ks][3] = f2tf32(Qs[(r0 + 8)*QKS + kk + qd + 4]);
        }
    }

    float co[2][4] = {{0,0,0,0},{0,0,0,0}};

    for (int kt = 0; kt <= tile; kt++) {
        const int k0 = kt * ATK;
        __syncthreads();

        {
            int r = k0 + rv;
            float4 kv0 = {0,0,0,0}, kv1 = {0,0,0,0}, vv0 = {0,0,0,0}, vv1 = {0,0,0,0};
            if (r < TT) {
                const float4* ks = reinterpret_cast<const float4*>(
                    &g_qkv[((long)(b*TT + r))*QKVN + 256 + h*DHH + sub*8]);
                kv0 = ks[0]; kv1 = ks[1];
                const float4* vs = reinterpret_cast<const float4*>(
                    &g_qkv[((long)(b*TT + r))*QKVN + 512 + h*DHH + sub*8]);
                vv0 = vs[0]; vv1 = vs[1];
            }
            float4* kd = reinterpret_cast<float4*>(&Ks[rv*QKS + sub*8]);
            kd[0] = kv0; kd[1] = kv1;
            float4* vd = reinterpret_cast<float4*>(&Vs[rv*QKS + sub*8]);
            vd[0] = vv0; vd[1] = vv1;
        }
        __syncthreads();

        float cs[4][4];
        #pragma unroll
        for (int ni = 0; ni < 4; ni++)
            #pragma unroll
            for (int j = 0; j < 4; j++) cs[ni][j] = 0.0f;
        #pragma unroll
        for (int ks = 0; ks < 4; ks++) {
            int kk = ks*8;
            unsigned bf[4][2];
            #pragma unroll
            for (int ni = 0; ni < 4; ni++) {
                int kn = wn*32 + ni*8 + grp;
                bf[ni][0] = f2tf32(Ks[kn*QKS + kk + qd    ]);
                bf[ni][1] = f2tf32(Ks[kn*QKS + kk + qd + 4]);
            }
            #pragma unroll
            for (int ni = 0; ni < 4; ni++)
                mma_tf32(cs[ni], aq[ks], bf[ni][0], bf[ni][1]);
        }

        const int r0 = wm*16 + grp;
        #pragma unroll
        for (int rr = 0; rr < 2; rr++) {
            int rl = r0 + rr*8;
            int q  = q0 + rl;
            bool qvalid = (q < TT);
            #pragma unroll
            for (int ni = 0; ni < 4; ni++) {
                int cl = wn*32 + ni*8 + 2*qd;
                int kc = k0 + cl;
                float v0, v1;
                if (kc > q || !qvalid) v0 = -1e30f;
                else {
                    float bias = adaptive ? g_h[((long)b*TT + q)*TT + kc] : 0.0f;
                    v0 = cs[ni][rr*2 + 0]*scale + bias;
                }
                if (kc + 1 > q || !qvalid) v1 = -1e30f;
                else {
                    float bias = adaptive ? g_h[((long)b*TT + q)*TT + kc + 1] : 0.0f;
                    v1 = cs[ni][rr*2 + 1]*scale + bias;
                }
                float2 sv; sv.x = v0; sv.y = v1;
                *reinterpret_cast<float2*>(&Ps[rl*PSS + cl]) = sv;
            }
        }
        __syncthreads();

        {
            float* pr = &Ps[rv*PSS + sub*16];
            float tmax = -1e30f;
            #pragma unroll
            for (int j = 0; j < 16; j++) tmax = fmaxf(tmax, pr[j]);
            tmax = fmaxf(tmax, __shfl_xor_sync(0xffffffffu, tmax, 1));
            tmax = fmaxf(tmax, __shfl_xor_sync(0xffffffffu, tmax, 2));
            float m_old = m_s[rv];
            float m_new = fmaxf(m_old, tmax);
            float tsum = 0.0f;
            #pragma unroll
            for (int j = 0; j < 16; j++) {
                float p = __expf(pr[j] - m_new);
                pr[j] = p;
                tsum += p;
            }
            tsum += __shfl_xor_sync(0xffffffffu, tsum, 1);
            tsum += __shfl_xor_sync(0xffffffffu, tsum, 2);
            if (sub == 0) {
                float corr = __expf(m_old - m_new);
                corr_s[rv] = corr;
                l_s[rv]    = l_s[rv]*corr + tsum;
                m_s[rv]    = m_new;
            }
        }
        __syncthreads();

        {
            float c0f = corr_s[r0];
            float c1f = corr_s[r0 + 8];
            #pragma unroll
            for (int nj = 0; nj < 2; nj++) {
                co[nj][0] *= c0f; co[nj][1] *= c0f;
                co[nj][2] *= c1f; co[nj][3] *= c1f;
            }
            #pragma unroll
            for (int ks = 0; ks < 8; ks++) {
                int kk = ks*8;
                unsigned ap[4];
                ap[0] = f2tf32(Ps[(r0    )*PSS + kk + qd    ]);
                ap[1] = f2tf32(Ps[(r0 + 8)*PSS + kk + qd    ]);
                ap[2] = f2tf32(Ps[(r0    )*PSS + kk + qd + 4]);
                ap[3] = f2tf32(Ps[(r0 + 8)*PSS + kk + qd + 4]);
                #pragma unroll
                for (int nj = 0; nj < 2; nj++) {
                    int nc = wn*16 + nj*8 + grp;
                    unsigned b0 = f2tf32(Vs[(kk + qd    )*QKS + nc]);
                    unsigned b1 = f2tf32(Vs[(kk + qd + 4)*QKS + nc]);
                    mma_tf32(co[nj], ap, b0, b1);
                }
            }
        }
    }

    {
        const int r0 = wm*16 + grp;
        int qa = q0 + r0, qb = q0 + r0 + 8;
        float inva = (qa < TT) ? 1.0f / l_s[r0]     : 0.0f;
        float invb = (qb < TT) ? 1.0f / l_s[r0 + 8] : 0.0f;
        #pragma unroll
        for (int nj = 0; nj < 2; nj++) {
            int col = wn*16 + nj*8 + 2*qd;
            if (qa < TT) {
                float2 ov; ov.x = tf32r(co[nj][0]*inva); ov.y = tf32r(co[nj][1]*inva);
                *reinterpret_cast<float2*>(&g_y[((long)(b*TT + qa))*CC + h*DHH + col]) = ov;
            }
            if (qb < TT) {
                float2 ov; ov.x = tf32r(co[nj][2]*invb); ov.y = tf32r(co[nj][3]*invb);
                *reinterpret_cast<float2*>(&g_y[((long)(b*TT + qb))*CC + h*DHH + col]) = ov;
            }
        }
    }
}

// ---------------- launch ----------------
extern "C" void kernel_launch(void* const* d_in, const int* in_sizes, int n_in,
                              void* d_out, int out_size) {
    const float* dc      = (const float*)d_in[0];
    const float* z       = (const float*)d_in[1];
    const float* p1      = (const float*)d_in[2];
    const float* p2      = (const float*)d_in[3];
    const float* p3      = (const float*)d_in[4];
    const float* frame   = (const float*)d_in[5];
    const float* cam     = (const float*)d_in[6];
    const float* timee   = (const float*)d_in[7];
    const float* locW1   = (const float*)d_in[8];
    const float* locb1   = (const float*)d_in[9];
    const float* locW2   = (const float*)d_in[10];
    const float* locb2   = (const float*)d_in[11];
    const float* ln1w    = (const float*)d_in[12];
    const float* ln1b    = (const float*)d_in[13];
    const float* Wq      = (const float*)d_in[14];
    const float* bq      = (const float*)d_in[15];
    const float* Wk      = (const float*)d_in[16];
    const float* bk      = (const float*)d_in[17];
    const float* Wv      = (const float*)d_in[18];
    const float* bv      = (const float*)d_in[19];
    const float* Wo      = (const float*)d_in[20];
    const float* bo      = (const float*)d_in[21];
    const float* ln2w    = (const float*)d_in[22];
    const float* ln2b    = (const float*)d_in[23];
    const float* W1      = (const float*)d_in[24];
    const float* b1      = (const float*)d_in[25];
    const float* W2      = (const float*)d_in[26];
    const float* b2      = (const float*)d_in[27];
    const float* lnfw    = (const float*)d_in[28];
    const float* lnfb    = (const float*)d_in[29];
    const float* headW   = (const float*)d_in[30];

    float *xp, *xnp, *qkvp, *yp, *ffnp, *wqkvp, *bqkvp, *worp, *w1rp, *w2rp, *hdrp;
    cudaGetSymbolAddress((void**)&xp,    g_x);
    cudaGetSymbolAddress((void**)&xnp,   g_xn);
    cudaGetSymbolAddress((void**)&qkvp,  g_qkv);
    cudaGetSymbolAddress((void**)&yp,    g_y);
    cudaGetSymbolAddress((void**)&ffnp,  g_ffn);
    cudaGetSymbolAddress((void**)&wqkvp, g_wqkv);
    cudaGetSymbolAddress((void**)&bqkvp, g_bqkv);
    cudaGetSymbolAddress((void**)&worp,  g_wor);
    cudaGetSymbolAddress((void**)&w1rp,  g_w1r);
    cudaGetSymbolAddress((void**)&w2rp,  g_w2r);
    cudaGetSymbolAddress((void**)&hdrp,  g_hdr);

    const int MB128 = (MM + 127) / 128;  // 26
    dim3 g_qkvg(QKVN/64, MB128);
    dim3 g_cc(CC/64, MB128);
    dim3 g_ff(FF/64, MB128);
    dim3 attn_grid((TT + ATQ - 1)/ATQ, BB*HH);

    {
        long np = (long)LL*QKVN*CC + (long)LL*QKVN;
        pack_qkv_kernel<<<(int)((np + 255) / 256), 256>>>(Wq, Wk, Wv, bq, bk, bv);
        long nr = (long)LL*CC*CC + (long)LL*FF*CC + (long)LL*CC*FF + (long)VOC*CC;
        round_w_kernel<<<(int)((nr + 255) / 256), 256>>>(Wo, W1, W2, headW);
    }
    embed_kernel<<<(MM*CC + 255) / 256, 256>>>(dc, z, frame, cam, timee);

    for (int l = 0; l < LL; l++) {
        ln_kernel<<<MM, CC>>>(xp, ln1w + l*CC, ln1b + l*CC, xnp);

        gemm_tc<128,false,false,true><<<g_qkvg, 256>>>(xnp, CC, wqkvp + (long)l*QKVN*CC,
                                                       bqkvp + l*QKVN, nullptr, qkvp, QKVN,
                                                       MM, QKVN, CC);

        if (l == 0) {
            long nh = (long)BB*TT*TT;
            zero_h_kernel<<<(int)((nh + 255) / 256), 256>>>();
            loc1_kernel<<<3*BB, 64>>>(p1, p2, p3, locW1, locb1);
            loc2_kernel<<<(3*BB*65536 + 127) / 128, 128>>>(locW2, locb2);
        }

        attn_kernel<<<attn_grid, 256>>>((l % 2 == 0) ? 1 : 0);

        gemm_tc<128,false,true,false><<<g_cc, 256>>>(yp, CC, worp + (long)l*CC*CC, bo + l*CC,
                                                     xp, xp, CC, MM, CC, CC);

        ln_kernel<<<MM, CC>>>(xp, ln2w + l*CC, ln2b + l*CC, xnp);

        gemm_tc<128,true,false,true><<<g_ff, 256>>>(xnp, CC, w1rp + (long)l*FF*CC, b1 + (long)l*FF,
                                                    nullptr, ffnp, FF, MM, FF, CC);
        gemm_tc<128,false,true,false><<<g_cc, 256>>>(ffnp, FF, w2rp + (long)l*CC*FF, b2 + l*CC,
                                                     xp, xp, CC, MM, CC, FF);
    }

    ln_kernel<<<MM, CC>>>(xp, lnfw, lnfb, xnp);

    dim3 g_head(VOC/64, MB128);
    gemm_tc<128,false,false,false><<<g_head, 256>>>(xnp, CC, hdrp, nullptr, nullptr,
                                                    (float*)d_out, VOC, MM, VOC, CC);
}

// round 17
// speedup vs baseline: 1.0793x; 1.0126x over previous
#include <cuda_runtime.h>
#include <math.h>

// ---------------- problem constants ----------------
#define BB   4
#define TT   827
#define CC   256
#define HH   8
#define DHH  32
#define LL   12
#define FF   1024            // 4*C
#define MM   (BB*TT)         // 3308 rows
#define VOC  16384
#define QKVN 768

// ---------------- scratch (device globals; no allocs allowed) ----------------
__device__ float g_x   [MM*CC];
__device__ float g_xn  [MM*CC];
__device__ float g_qkv [MM*QKVN];
__device__ float g_y   [MM*CC];
__device__ float g_ffn [MM*FF];
__device__ float g_h   [(long)BB*TT*TT];
__device__ float g_z1  [3*BB*60];
__device__ float g_wqkv[(long)LL*QKVN*CC]; // packed + tf32-rounded
__device__ float g_bqkv[LL*QKVN];
__device__ float g_wor [(long)LL*CC*CC];   // tf32-rounded Wo
__device__ float g_w1r [(long)LL*FF*CC];   // tf32-rounded W1
__device__ float g_w2r [(long)LL*CC*FF];   // tf32-rounded W2
__device__ float g_hdr [(long)VOC*CC];     // tf32-rounded head_W

__device__ __forceinline__ float gelu_exact(float z) {
    return 0.5f * z * (1.0f + erff(z * 0.70710678118654752f));
}

__device__ __forceinline__ unsigned f2tf32(float x) {
    unsigned r;
    asm("cvt.rna.tf32.f32 %0, %1;" : "=r"(r) : "f"(x));
    return r;
}
__device__ __forceinline__ float tf32r(float x) {
    return __uint_as_float(f2tf32(x));
}

__device__ __forceinline__ void mma_tf32(float c[4], const unsigned a[4],
                                         unsigned b0, unsigned b1) {
    asm volatile(
        "mma.sync.aligned.m16n8k8.row.col.f32.tf32.tf32.f32 "
        "{%0,%1,%2,%3},{%4,%5,%6,%7},{%8,%9},{%0,%1,%2,%3};"
        : "+f"(c[0]), "+f"(c[1]), "+f"(c[2]), "+f"(c[3])
        : "r"(a[0]), "r"(a[1]), "r"(a[2]), "r"(a[3]), "r"(b0), "r"(b1));
}

// ---------------- fused QKV weight+bias packing (weights tf32-rounded) ----------------
__global__ void pack_qkv_kernel(const float* __restrict__ Wq, const float* __restrict__ Wk,
                                const float* __restrict__ Wv, const float* __restrict__ bq,
                                const float* __restrict__ bk, const float* __restrict__ bv) {
    const long nw = (long)LL*QKVN*CC;
    long idx = (long)blockIdx.x * blockDim.x + threadIdx.x;
    if (idx < nw) {
        int k = (int)(idx % CC);
        int n = (int)((idx / CC) % QKVN);
        int l = (int)(idx / ((long)CC*QKVN));
        const float* src;
        if      (n < 256) src = &Wq[((long)l*256 + n      )*CC];
        else if (n < 512) src = &Wk[((long)l*256 + n - 256)*CC];
        else              src = &Wv[((long)l*256 + n - 512)*CC];
        g_wqkv[idx] = tf32r(src[k]);
    } else if (idx < nw + (long)LL*QKVN) {
        int r = (int)(idx - nw);
        int n = r % QKVN;
        int l = r / QKVN;
        float v;
        if      (n < 256) v = bq[l*256 + n];
        else if (n < 512) v = bk[l*256 + n - 256];
        else              v = bv[l*256 + n - 512];
        g_bqkv[r] = v;
    }
}

// ---------------- round remaining weights to tf32 ----------------
__global__ void round_w_kernel(const float* __restrict__ Wo, const float* __restrict__ W1,
                               const float* __restrict__ W2, const float* __restrict__ headW) {
    const long nWo = (long)LL*CC*CC;
    const long nW1 = (long)LL*FF*CC;
    const long nW2 = (long)LL*CC*FF;
    const long nH  = (long)VOC*CC;
    long idx = (long)blockIdx.x * blockDim.x + threadIdx.x;
    if (idx < nWo)                        g_wor[idx]                 = tf32r(Wo[idx]);
    else if (idx < nWo + nW1)             g_w1r[idx - nWo]           = tf32r(W1[idx - nWo]);
    else if (idx < nWo + nW1 + nW2)       g_w2r[idx - nWo - nW1]     = tf32r(W2[idx - nWo - nW1]);
    else if (idx < nWo + nW1 + nW2 + nH)  g_hdr[idx - nWo - nW1 - nW2] = tf32r(headW[idx - nWo - nW1 - nW2]);
}

// ---------------- locality MLP ----------------
__global__ void loc1_kernel(const float* __restrict__ p1, const float* __restrict__ p2,
                            const float* __restrict__ p3, const float* __restrict__ W1,
                            const float* __restrict__ b1) {
    int mat = blockIdx.x / BB;
    int b   = blockIdx.x % BB;
    int j   = threadIdx.x;
    if (j >= 60) return;
    const float* p = (mat == 0) ? p1 : (mat == 1) ? p2 : p3;
    float s = b1[j];
    #pragma unroll
    for (int i = 0; i < 30; i++) s += p[b*30 + i] * W1[j*30 + i];
    g_z1[(mat*BB + b)*60 + j] = gelu_exact(s);
}

__global__ void zero_h_kernel() {
    long i = (long)blockIdx.x * blockDim.x + threadIdx.x;
    if (i < (long)BB*TT*TT) g_h[i] = 0.0f;
}

__global__ void loc2_kernel(const float* __restrict__ W2, const float* __restrict__ b2) {
    int idx = blockIdx.x * blockDim.x + threadIdx.x;
    const int total = 3 * BB * 65536;
    if (idx >= total) return;
    int mat = idx / (BB * 65536);
    int rem = idx % (BB * 65536);
    int b   = rem / 65536;
    int o   = rem % 65536;
    const float* z1 = &g_z1[(mat*BB + b)*60];
    const float* wr = &W2[(long)o * 60];
    float s = b2[o];
    #pragma unroll
    for (int j = 0; j < 60; j++) s += z1[j] * wr[j];
    int r = o >> 8, c = o & 255;
    int r0 = (mat == 0) ? 285 : 571;
    int c0 = (mat == 2) ? 286 : 0;
    g_h[((long)b*TT + (r0 + r))*TT + (c0 + c)] = s;
}

// ---------------- embedding ----------------
__global__ void embed_kernel(const float* __restrict__ dc, const float* __restrict__ z,
                             const float* __restrict__ frame, const float* __restrict__ cam,
                             const float* __restrict__ timee) {
    int idx = blockIdx.x * blockDim.x + threadIdx.x;
    if (idx >= MM*CC) return;
    int c = idx % CC;
    int t = (idx / CC) % TT;
    int b = idx / (CC * TT);
    float tok = (t < 572) ? dc[((long)b*572 + t)*CC + c]
                          : z [((long)b*256 + (t - 572))*CC + c];
    float role;
    if      (t < 256) role = frame[(t      )*CC + c];
    else if (t < 286) role = cam  [(t - 256)*CC + c];
    else if (t < 542) role = frame[(t - 286)*CC + c];
    else if (t < 572) role = cam  [(t - 542)*CC + c];
    else              role = frame[(t - 572)*CC + c];
    g_x[idx] = tok + role + timee[t*CC + c];
}

// ---------------- layernorm: warp per row, 8 rows/block, no block syncs ----------------
__global__ void __launch_bounds__(256) ln_kernel(const float* __restrict__ x,
                                                 const float* __restrict__ w,
                                                 const float* __restrict__ b,
                                                 float* __restrict__ out) {
    int wid = threadIdx.x >> 5;
    int lane = threadIdx.x & 31;
    int row = blockIdx.x * 8 + wid;
    if (row >= MM) return;

    const float4* r4 = reinterpret_cast<const float4*>(&x[(long)row*CC]);
    float4 v0 = r4[lane];
    float4 v1 = r4[lane + 32];

    float s1 = v0.x + v0.y + v0.z + v0.w + v1.x + v1.y + v1.z + v1.w;
    float s2 = v0.x*v0.x + v0.y*v0.y + v0.z*v0.z + v0.w*v0.w
             + v1.x*v1.x + v1.y*v1.y + v1.z*v1.z + v1.w*v1.w;
    #pragma unroll
    for (int o = 16; o; o >>= 1) {
        s1 += __shfl_xor_sync(0xffffffffu, s1, o);
        s2 += __shfl_xor_sync(0xffffffffu, s2, o);
    }
    float mean = s1 * (1.0f / CC);
    float var  = s2 * (1.0f / CC) - mean * mean;
    float rstd = rsqrtf(var + 1e-5f);

    const float4* w4 = reinterpret_cast<const float4*>(w);
    const float4* b4 = reinterpret_cast<const float4*>(b);
    float4* o4 = reinterpret_cast<float4*>(&out[(long)row*CC]);

    float4 wa = w4[lane],      ba = b4[lane];
    float4 wb = w4[lane + 32], bb = b4[lane + 32];
    float4 oa, ob;
    oa.x = tf32r((v0.x - mean)*rstd*wa.x + ba.x);
    oa.y = tf32r((v0.y - mean)*rstd*wa.y + ba.y);
    oa.z = tf32r((v0.z - mean)*rstd*wa.z + ba.z);
    oa.w = tf32r((v0.w - mean)*rstd*wa.w + ba.w);
    ob.x = tf32r((v1.x - mean)*rstd*wb.x + bb.x);
    ob.y = tf32r((v1.y - mean)*rstd*wb.y + bb.y);
    ob.z = tf32r((v1.z - mean)*rstd*wb.z + bb.z);
    ob.w = tf32r((v1.w - mean)*rstd*wb.w + bb.w);
    o4[lane]      = oa;
    o4[lane + 32] = ob;
}

// ---------------- TF32 GEMM: 2-stage, BK=32, no cvt in hot loop ----------------
// Dynamic smem: 2 stages x (BM+64) x 36 floats.
#define SM_STRIDE 36
#define BKK 32

__device__ __forceinline__ void cp_async16(unsigned dst, const void* src, int bytes) {
    asm volatile("cp.async.ca.shared.global [%0], [%1], 16, %2;\n"
                 :: "r"(dst), "l"(src), "r"(bytes));
}

template<int BM, bool DO_GELU, bool DO_RES, bool ROUND_OUT>
__global__ void __launch_bounds__(256)
gemm_tc(const float* __restrict__ A, int lda,
        const float* __restrict__ W,
        const float* __restrict__ bias,
        const float* __restrict__ res,
        float* __restrict__ out, int ldo,
        int M, int N, int K) {
    constexpr int MI = BM / 64;
    constexpr int ASZ = BM * SM_STRIDE;
    constexpr int BSZ = 64 * SM_STRIDE;
    extern __shared__ __align__(16) float smem[];
    float* As[2] = { smem,             smem + ASZ + BSZ };
    float* Bs[2] = { smem + ASZ,       smem + 2*ASZ + BSZ };

    const int tid  = threadIdx.x;
    const int m0   = blockIdx.y * BM;
    const int n0   = blockIdx.x * 64;
    const int warp = tid >> 5, lane = tid & 31;
    const int wm = warp >> 1, wn = warp & 1;
    const int grp = lane >> 2, qd = lane & 3;

    float c[MI][4][4];
    #pragma unroll
    for (int i = 0; i < MI; i++)
        #pragma unroll
        for (int j = 0; j < 4; j++)
            #pragma unroll
            for (int k = 0; k < 4; k++) c[i][j][k] = 0.0f;

    unsigned sA[2], sB[2];
    sA[0] = (unsigned)__cvta_generic_to_shared(As[0]);
    sA[1] = (unsigned)__cvta_generic_to_shared(As[1]);
    sB[0] = (unsigned)__cvta_generic_to_shared(Bs[0]);
    sB[1] = (unsigned)__cvta_generic_to_shared(Bs[1]);

    // staging: idx = tid + 256*i; row = idx>>3, col = (idx&7)*4  (BK=32 -> 8 float4/row)
    auto load_tiles = [&](int k0, int buf) {
        #pragma unroll
        for (int i = 0; i < MI*2; i++) {          // A: BM*32/4/256 = MI*2 chunks
            int idx = tid + 256*i;
            int r = idx >> 3, cl = (idx & 7) << 2;
            int m = m0 + r;
            const float* src = A + (long)(m < M ? m : 0) * lda + k0 + cl;
            cp_async16(sA[buf] + (r*SM_STRIDE + cl)*4, src, m < M ? 16 : 0);
        }
        #pragma unroll
        for (int i = 0; i < 2; i++) {             // B: 64*32/4/256 = 2 chunks
            int idx = tid + 256*i;
            int r = idx >> 3, cl = (idx & 7) << 2;
            const float* src = W + (long)(n0 + r) * K + k0 + cl;
            cp_async16(sB[buf] + (r*SM_STRIDE + cl)*4, src, 16);
        }
        asm volatile("cp.async.commit_group;\n");
    };

    auto compute = [&](int buf) {
        const unsigned* pa = reinterpret_cast<const unsigned*>(As[buf]);
        const unsigned* pb = reinterpret_cast<const unsigned*>(Bs[buf]);
        #pragma unroll
        for (int ks = 0; ks < 4; ks++) {
            const int kk = ks * 8;
            unsigned a[MI][4], b[4][2];
            #pragma unroll
            for (int mi = 0; mi < MI; mi++) {
                int r = wm*(16*MI) + mi*16 + grp;
                a[mi][0] = pa[(r    )*SM_STRIDE + kk + qd    ];
                a[mi][1] = pa[(r + 8)*SM_STRIDE + kk + qd    ];
                a[mi][2] = pa[(r    )*SM_STRIDE + kk + qd + 4];
                a[mi][3] = pa[(r + 8)*SM_STRIDE + kk + qd + 4];
            }
            #pragma unroll
            for (int ni = 0; ni < 4; ni++) {
                int n = wn*32 + ni*8 + grp;
                b[ni][0] = pb[n*SM_STRIDE + kk + qd    ];
                b[ni][1] = pb[n*SM_STRIDE + kk + qd + 4];
            }
            #pragma unroll
            for (int mi = 0; mi < MI; mi++)
                #pragma unroll
                for (int ni = 0; ni < 4; ni++)
                    mma_tf32(c[mi][ni], a[mi], b[ni][0], b[ni][1]);
        }
    };

    const int nt = K >> 5;
    load_tiles(0, 0);
    for (int t = 0; t < nt; t++) {
        const int buf = t & 1;
        if (t + 1 < nt) {
            load_tiles((t + 1) << 5, 1 - buf);
            asm volatile("cp.async.wait_group 1;\n");
        } else {
            asm volatile("cp.async.wait_group 0;\n");
        }
        __syncthreads();
        compute(buf);
        __syncthreads();
    }

    #pragma unroll
    for (int mi = 0; mi < MI; mi++) {
        #pragma unroll
        for (int ni = 0; ni < 4; ni++) {
            int col = n0 + wn*32 + ni*8 + 2*qd;
            float bsum0 = bias ? bias[col]     : 0.0f;
            float bsum1 = bias ? bias[col + 1] : 0.0f;
            #pragma unroll
            for (int rr = 0; rr < 2; rr++) {
                int row = m0 + wm*(16*MI) + mi*16 + grp + rr*8;
                if (row >= M) continue;
                float v0 = c[mi][ni][rr*2 + 0] + bsum0;
                float v1 = c[mi][ni][rr*2 + 1] + bsum1;
                if (DO_GELU) { v0 = gelu_exact(v0); v1 = gelu_exact(v1); }
                if (DO_RES) {
                    const float2 rv = *reinterpret_cast<const float2*>(&res[(long)row*ldo + col]);
                    v0 += rv.x; v1 += rv.y;
                }
                if (ROUND_OUT) { v0 = tf32r(v0); v1 = tf32r(v1); }
                float2 ov; ov.x = v0; ov.y = v1;
                *reinterpret_cast<float2*>(&out[(long)row*ldo + col]) = ov;
            }
        }
    }
}

// ---------------- tensor-core flash attention (R8-proven; output tf32-rounded) ----------------
#define ATQ 64
#define ATK 64
#define QKS 36
#define PSS 68

__global__ void __launch_bounds__(256) attn_kernel(int adaptive) {
    __shared__ __align__(16) float Qs[ATQ*QKS];
    __shared__ __align__(16) float Ks[ATK*QKS];
    __shared__ __align__(16) float Vs[ATK*QKS];
    __shared__ __align__(16) float Ps[ATQ*PSS];
    __shared__ float m_s[ATQ], l_s[ATQ], corr_s[ATQ];

    const int tile = blockIdx.x;
    const int bh   = blockIdx.y;
    const int b = bh >> 3, h = bh & 7;
    const int t = threadIdx.x;
    const int q0 = tile * ATQ;
    const int warp = t >> 5, lane = t & 31;
    const int wm = warp >> 1, wn = warp & 1;
    const int grp = lane >> 2, qd = lane & 3;
    const int rv = t >> 2, sub = t & 3;
    const float scale = 0.1767766952966369f;

    {
        int r = q0 + rv;
        float4 a0 = {0,0,0,0}, a1 = {0,0,0,0};
        if (r < TT) {
            const float4* src = reinterpret_cast<const float4*>(
                &g_qkv[((long)(b*TT + r))*QKVN + h*DHH + sub*8]);
            a0 = src[0]; a1 = src[1];
        }
        float4* qdst = reinterpret_cast<float4*>(&Qs[rv*QKS + sub*8]);
        qdst[0] = a0; qdst[1] = a1;
    }
    if (t < ATQ) { m_s[t] = -1e30f; l_s[t] = 0.0f; }
    __syncthreads();

    unsigned aq[4][4];
    {
        int r0 = wm*16 + grp;
        #pragma unroll
        for (int ks = 0; ks < 4; ks++) {
            int kk = ks*8;
            aq[ks][0] = f2tf32(Qs[(r0    )*QKS + kk + qd    ]);
            aq[ks][1] = f2tf32(Qs[(r0 + 8)*QKS + kk + qd    ]);
            aq[ks][2] = f2tf32(Qs[(r0    )*QKS + kk + qd + 4]);
            aq[ks][3] = f2tf32(Qs[(r0 + 8)*QKS + kk + qd + 4]);
        }
    }

    float co[2][4] = {{0,0,0,0},{0,0,0,0}};

    for (int kt = 0; kt <= tile; kt++) {
        const int k0 = kt * ATK;
        __syncthreads();

        {
            int r = k0 + rv;
            float4 kv0 = {0,0,0,0}, kv1 = {0,0,0,0}, vv0 = {0,0,0,0}, vv1 = {0,0,0,0};
            if (r < TT) {
                const float4* ks = reinterpret_cast<const float4*>(
                    &g_qkv[((long)(b*TT + r))*QKVN + 256 + h*DHH + sub*8]);
                kv0 = ks[0]; kv1 = ks[1];
                const float4* vs = reinterpret_cast<const float4*>(
                    &g_qkv[((long)(b*TT + r))*QKVN + 512 + h*DHH + sub*8]);
                vv0 = vs[0]; vv1 = vs[1];
            }
            float4* kd = reinterpret_cast<float4*>(&Ks[rv*QKS + sub*8]);
            kd[0] = kv0; kd[1] = kv1;
            float4* vd = reinterpret_cast<float4*>(&Vs[rv*QKS + sub*8]);
            vd[0] = vv0; vd[1] = vv1;
        }
        __syncthreads();

        float cs[4][4];
        #pragma unroll
        for (int ni = 0; ni < 4; ni++)
            #pragma unroll
            for (int j = 0; j < 4; j++) cs[ni][j] = 0.0f;
        #pragma unroll
        for (int ks = 0; ks < 4; ks++) {
            int kk = ks*8;
            unsigned bf[4][2];
            #pragma unroll
            for (int ni = 0; ni < 4; ni++) {
                int kn = wn*32 + ni*8 + grp;
                bf[ni][0] = f2tf32(Ks[kn*QKS + kk + qd    ]);
                bf[ni][1] = f2tf32(Ks[kn*QKS + kk + qd + 4]);
            }
            #pragma unroll
            for (int ni = 0; ni < 4; ni++)
                mma_tf32(cs[ni], aq[ks], bf[ni][0], bf[ni][1]);
        }

        const int r0 = wm*16 + grp;
        #pragma unroll
        for (int rr = 0; rr < 2; rr++) {
            int rl = r0 + rr*8;
            int q  = q0 + rl;
            bool qvalid = (q < TT);
            #pragma unroll
            for (int ni = 0; ni < 4; ni++) {
                int cl = wn*32 + ni*8 + 2*qd;
                int kc = k0 + cl;
                float v0, v1;
                if (kc > q || !qvalid) v0 = -1e30f;
                else {
                    float bias = adaptive ? g_h[((long)b*TT + q)*TT + kc] : 0.0f;
                    v0 = cs[ni][rr*2 + 0]*scale + bias;
                }
                if (kc + 1 > q || !qvalid) v1 = -1e30f;
                else {
                    float bias = adaptive ? g_h[((long)b*TT + q)*TT + kc + 1] : 0.0f;
                    v1 = cs[ni][rr*2 + 1]*scale + bias;
                }
                float2 sv; sv.x = v0; sv.y = v1;
                *reinterpret_cast<float2*>(&Ps[rl*PSS + cl]) = sv;
            }
        }
        __syncthreads();

        {
            float* pr = &Ps[rv*PSS + sub*16];
            float tmax = -1e30f;
            #pragma unroll
            for (int j = 0; j < 16; j++) tmax = fmaxf(tmax, pr[j]);
            tmax = fmaxf(tmax, __shfl_xor_sync(0xffffffffu, tmax, 1));
            tmax = fmaxf(tmax, __shfl_xor_sync(0xffffffffu, tmax, 2));
            float m_old = m_s[rv];
            float m_new = fmaxf(m_old, tmax);
            float tsum = 0.0f;
            #pragma unroll
            for (int j = 0; j < 16; j++) {
                float p = __expf(pr[j] - m_new);
                pr[j] = p;
                tsum += p;
            }
            tsum += __shfl_xor_sync(0xffffffffu, tsum, 1);
            tsum += __shfl_xor_sync(0xffffffffu, tsum, 2);
            if (sub == 0) {
                float corr = __expf(m_old - m_new);
                corr_s[rv] = corr;
                l_s[rv]    = l_s[rv]*corr + tsum;
                m_s[rv]    = m_new;
            }
        }
        __syncthreads();

        {
            float c0f = corr_s[r0];
            float c1f = corr_s[r0 + 8];
            #pragma unroll
            for (int nj = 0; nj < 2; nj++) {
                co[nj][0] *= c0f; co[nj][1] *= c0f;
                co[nj][2] *= c1f; co[nj][3] *= c1f;
            }
            #pragma unroll
            for (int ks = 0; ks < 8; ks++) {
                int kk = ks*8;
                unsigned ap[4];
                ap[0] = f2tf32(Ps[(r0    )*PSS + kk + qd    ]);
                ap[1] = f2tf32(Ps[(r0 + 8)*PSS + kk + qd    ]);
                ap[2] = f2tf32(Ps[(r0    )*PSS + kk + qd + 4]);
                ap[3] = f2tf32(Ps[(r0 + 8)*PSS + kk + qd + 4]);
                #pragma unroll
                for (int nj = 0; nj < 2; nj++) {
                    int nc = wn*16 + nj*8 + grp;
                    unsigned b0 = f2tf32(Vs[(kk + qd    )*QKS + nc]);
                    unsigned b1 = f2tf32(Vs[(kk + qd + 4)*QKS + nc]);
                    mma_tf32(co[nj], ap, b0, b1);
                }
            }
        }
    }

    {
        const int r0 = wm*16 + grp;
        int qa = q0 + r0, qb = q0 + r0 + 8;
        float inva = (qa < TT) ? 1.0f / l_s[r0]     : 0.0f;
        float invb = (qb < TT) ? 1.0f / l_s[r0 + 8] : 0.0f;
        #pragma unroll
        for (int nj = 0; nj < 2; nj++) {
            int col = wn*16 + nj*8 + 2*qd;
            if (qa < TT) {
                float2 ov; ov.x = tf32r(co[nj][0]*inva); ov.y = tf32r(co[nj][1]*inva);
                *reinterpret_cast<float2*>(&g_y[((long)(b*TT + qa))*CC + h*DHH + col]) = ov;
            }
            if (qb < TT) {
                float2 ov; ov.x = tf32r(co[nj][2]*invb); ov.y = tf32r(co[nj][3]*invb);
                *reinterpret_cast<float2*>(&g_y[((long)(b*TT + qb))*CC + h*DHH + col]) = ov;
            }
        }
    }
}

// ---------------- launch ----------------
extern "C" void kernel_launch(void* const* d_in, const int* in_sizes, int n_in,
                              void* d_out, int out_size) {
    const float* dc      = (const float*)d_in[0];
    const float* z       = (const float*)d_in[1];
    const float* p1      = (const float*)d_in[2];
    const float* p2      = (const float*)d_in[3];
    const float* p3      = (const float*)d_in[4];
    const float* frame   = (const float*)d_in[5];
    const float* cam     = (const float*)d_in[6];
    const float* timee   = (const float*)d_in[7];
    const float* locW1   = (const float*)d_in[8];
    const float* locb1   = (const float*)d_in[9];
    const float* locW2   = (const float*)d_in[10];
    const float* locb2   = (const float*)d_in[11];
    const float* ln1w    = (const float*)d_in[12];
    const float* ln1b    = (const float*)d_in[13];
    const float* Wq      = (const float*)d_in[14];
    const float* bq      = (const float*)d_in[15];
    const float* Wk      = (const float*)d_in[16];
    const float* bk      = (const float*)d_in[17];
    const float* Wv      = (const float*)d_in[18];
    const float* bv      = (const float*)d_in[19];
    const float* Wo      = (const float*)d_in[20];
    const float* bo      = (const float*)d_in[21];
    const float* ln2w    = (const float*)d_in[22];
    const float* ln2b    = (const float*)d_in[23];
    const float* W1      = (const float*)d_in[24];
    const float* b1      = (const float*)d_in[25];
    const float* W2      = (const float*)d_in[26];
    const float* b2      = (const float*)d_in[27];
    const float* lnfw    = (const float*)d_in[28];
    const float* lnfb    = (const float*)d_in[29];
    const float* headW   = (const float*)d_in[30];

    float *xp, *xnp, *qkvp, *yp, *ffnp, *wqkvp, *bqkvp, *worp, *w1rp, *w2rp, *hdrp;
    cudaGetSymbolAddress((void**)&xp,    g_x);
    cudaGetSymbolAddress((void**)&xnp,   g_xn);
    cudaGetSymbolAddress((void**)&qkvp,  g_qkv);
    cudaGetSymbolAddress((void**)&yp,    g_y);
    cudaGetSymbolAddress((void**)&ffnp,  g_ffn);
    cudaGetSymbolAddress((void**)&wqkvp, g_wqkv);
    cudaGetSymbolAddress((void**)&bqkvp, g_bqkv);
    cudaGetSymbolAddress((void**)&worp,  g_wor);
    cudaGetSymbolAddress((void**)&w1rp,  g_w1r);
    cudaGetSymbolAddress((void**)&w2rp,  g_w2r);
    cudaGetSymbolAddress((void**)&hdrp,  g_hdr);

    // dynamic smem size for BM=128 GEMM: 2 * (128+64) * 36 * 4 = 55296 B
    const int GSMEM = 2 * (128 + 64) * SM_STRIDE * 4;
    cudaFuncSetAttribute(gemm_tc<128,false,false,true>,  cudaFuncAttributeMaxDynamicSharedMemorySize, GSMEM);
    cudaFuncSetAttribute(gemm_tc<128,false,true,false>,  cudaFuncAttributeMaxDynamicSharedMemorySize, GSMEM);
    cudaFuncSetAttribute(gemm_tc<128,true,false,true>,   cudaFuncAttributeMaxDynamicSharedMemorySize, GSMEM);
    cudaFuncSetAttribute(gemm_tc<128,false,false,false>, cudaFuncAttributeMaxDynamicSharedMemorySize, GSMEM);

    const int MB128 = (MM + 127) / 128;  // 26
    dim3 g_qkvg(QKVN/64, MB128);
    dim3 g_cc(CC/64, MB128);
    dim3 g_ff(FF/64, MB128);
    dim3 attn_grid((TT + ATQ - 1)/ATQ, BB*HH);
    const int LNB = (MM + 7) / 8;        // 414

    {
        long np = (long)LL*QKVN*CC + (long)LL*QKVN;
        pack_qkv_kernel<<<(int)((np + 255) / 256), 256>>>(Wq, Wk, Wv, bq, bk, bv);
        long nr = (long)LL*CC*CC + (long)LL*FF*CC + (long)LL*CC*FF + (long)VOC*CC;
        round_w_kernel<<<(int)((nr + 255) / 256), 256>>>(Wo, W1, W2, headW);
    }
    embed_kernel<<<(MM*CC + 255) / 256, 256>>>(dc, z, frame, cam, timee);

    for (int l = 0; l < LL; l++) {
        ln_kernel<<<LNB, 256>>>(xp, ln1w + l*CC, ln1b + l*CC, xnp);

        gemm_tc<128,false,false,true><<<g_qkvg, 256, GSMEM>>>(xnp, CC, wqkvp + (long)l*QKVN*CC,
                                                              bqkvp + l*QKVN, nullptr, qkvp, QKVN,
                                                              MM, QKVN, CC);

        if (l == 0) {
            long nh = (long)BB*TT*TT;
            zero_h_kernel<<<(int)((nh + 255) / 256), 256>>>();
            loc1_kernel<<<3*BB, 64>>>(p1, p2, p3, locW1, locb1);
            loc2_kernel<<<(3*BB*65536 + 127) / 128, 128>>>(locW2, locb2);
        }

        attn_kernel<<<attn_grid, 256>>>((l % 2 == 0) ? 1 : 0);

        gemm_tc<128,false,true,false><<<g_cc, 256, GSMEM>>>(yp, CC, worp + (long)l*CC*CC, bo + l*CC,
                                                            xp, xp, CC, MM, CC, CC);

        ln_kernel<<<LNB, 256>>>(xp, ln2w + l*CC, ln2b + l*CC, xnp);

        gemm_tc<128,true,false,true><<<g_ff, 256, GSMEM>>>(xnp, CC, w1rp + (long)l*FF*CC, b1 + (long)l*FF,
                                                           nullptr, ffnp, FF, MM, FF, CC);
        gemm_tc<128,false,true,false><<<g_cc, 256, GSMEM>>>(ffnp, FF, w2rp + (long)l*CC*FF, b2 + l*CC,
                                                            xp, xp, CC, MM, CC, FF);
    }

    ln_kernel<<<LNB, 256>>>(xp, lnfw, lnfb, xnp);

    dim3 g_head(VOC/64, MB128);
    gemm_tc<128,false,false,false><<<g_head, 256, GSMEM>>>(xnp, CC, hdrp, nullptr, nullptr,
                                                           (float*)d_out, VOC, MM, VOC, CC);
}